// round 1
// baseline (speedup 1.0000x reference)
#include <cuda_runtime.h>

#define N_NODES 50000
#define N_EDGES 800000
#define HID 64
#define N_LAYERS 3
#define N_GRAPHS 64

// ---------------- scratch (device globals; no allocation allowed) ----------------
__device__ float g_buf0[N_NODES * HID];
__device__ float g_buf1[N_NODES * HID];
__device__ int   g_deg[N_NODES];
__device__ int   g_rowptr[N_NODES];
__device__ int   g_fill[N_NODES];
__device__ int   g_perm[N_EDGES];
__device__ float g_sattr[N_NODES];
__device__ float g_c1[N_LAYERS][HID];
__device__ float g_c2[N_LAYERS][HID];
__device__ float g_gsum[N_GRAPHS];
__device__ int   g_gcnt[N_GRAPHS];

// ---------------- init ----------------
__global__ void k_init() {
    int i = blockIdx.x * blockDim.x + threadIdx.x;
    if (i < N_NODES) { g_deg[i] = 0; g_fill[i] = 0; g_sattr[i] = 0.f; }
    if (i < N_GRAPHS) { g_gsum[i] = 0.f; g_gcnt[i] = 0; }
}

// ---------------- edge pass 1: in-degree + scalar edge_attr segment sum ----------------
__global__ void k_edge1(const int* __restrict__ ei, const float* __restrict__ ea) {
    int e = blockIdx.x * blockDim.x + threadIdx.x;
    if (e >= N_EDGES) return;
    int d = ei[N_EDGES + e];
    atomicAdd(&g_deg[d], 1);
    atomicAdd(&g_sattr[d], ea[e]);
}

// ---------------- exclusive prefix sum over deg (single block) ----------------
__global__ void k_scan() {
    __shared__ int partial[1024];
    const int tid = threadIdx.x;
    const int CH = (N_NODES + 1023) / 1024;  // 49
    const int base = tid * CH;
    int sum = 0;
    for (int i = 0; i < CH; i++) {
        int idx = base + i;
        if (idx < N_NODES) sum += g_deg[idx];
    }
    partial[tid] = sum;
    __syncthreads();
    for (int off = 1; off < 1024; off <<= 1) {
        int v = 0;
        if (tid >= off) v = partial[tid - off];
        __syncthreads();
        if (tid >= off) partial[tid] += v;
        __syncthreads();
    }
    int run = (tid == 0) ? 0 : partial[tid - 1];
    for (int i = 0; i < CH; i++) {
        int idx = base + i;
        if (idx < N_NODES) {
            g_rowptr[idx] = run;
            run += g_deg[idx];
        }
    }
}

// ---------------- edge pass 2: bucket-place src into CSR order ----------------
__global__ void k_edge2(const int* __restrict__ ei) {
    int e = blockIdx.x * blockDim.x + threadIdx.x;
    if (e >= N_EDGES) return;
    int s = ei[e];
    int d = ei[N_EDGES + e];
    int pos = g_rowptr[d] + atomicAdd(&g_fill[d], 1);
    g_perm[pos] = s;
}

// ---------------- per-layer rank-2 constants: c1 = edge_w @ W2, c2 = edge_b @ W2 ----------------
__global__ void k_const(const float* __restrict__ ew, const float* __restrict__ eb,
                        const float* __restrict__ nw) {
    int tid = threadIdx.x;
    if (tid >= N_LAYERS * HID) return;
    int l = tid / HID, h = tid % HID;
    float a = 0.f, b = 0.f;
    for (int k = 0; k < HID; k++) {
        float w = nw[(l * 2 * HID + HID + k) * HID + h];  // W2[k][h]
        a += ew[l * HID + k] * w;
        b += eb[l * HID + k] * w;
    }
    g_c1[l][h] = a;
    g_c2[l][h] = b;
}

// ---------------- fused layer: CSR gather-sum + node MLP + ReLU ----------------
__global__ void __launch_bounds__(256) k_layer(
    const float* __restrict__ xin, float* __restrict__ xout,
    const float* __restrict__ nw, const float* __restrict__ nb, int l)
{
    __shared__ float sW[HID][HID + 2];  // W1, padded: float2 reads conflict-free-ish
    __shared__ float sA[8][HID];
    const int tid = threadIdx.x;

    // stage W1[k][h] = node_w[l][k][h]
    for (int i = tid; i < HID * HID; i += 256) {
        int k = i / HID, h = i % HID;
        sW[k][h] = nw[(l * 2 * HID + k) * HID + h];
    }
    __syncthreads();

    const int warp = tid >> 5, lane = tid & 31;
    const int n = blockIdx.x * 8 + warp;
    if (n >= N_NODES) return;

    const int beg = g_rowptr[n];
    const int cnt = g_deg[n];

    // segmented sum of x[src] rows; 4-way unroll for MLP
    const float2* __restrict__ x2 = (const float2*)xin;
    float2 a0 = {0.f, 0.f}, a1 = {0.f, 0.f}, a2 = {0.f, 0.f}, a3 = {0.f, 0.f};
    int i = 0;
    for (; i + 4 <= cnt; i += 4) {
        int s0 = g_perm[beg + i + 0];
        int s1 = g_perm[beg + i + 1];
        int s2 = g_perm[beg + i + 2];
        int s3 = g_perm[beg + i + 3];
        float2 v0 = x2[s0 * 32 + lane];
        float2 v1 = x2[s1 * 32 + lane];
        float2 v2 = x2[s2 * 32 + lane];
        float2 v3 = x2[s3 * 32 + lane];
        a0.x += v0.x; a0.y += v0.y;
        a1.x += v1.x; a1.y += v1.y;
        a2.x += v2.x; a2.y += v2.y;
        a3.x += v3.x; a3.y += v3.y;
    }
    for (; i < cnt; i++) {
        int s = g_perm[beg + i];
        float2 v = x2[s * 32 + lane];
        a0.x += v.x; a0.y += v.y;
    }
    float accx = a0.x + a1.x + a2.x + a3.x;
    float accy = a0.y + a1.y + a2.y + a3.y;

    sA[warp][2 * lane + 0] = accx;
    sA[warp][2 * lane + 1] = accy;
    __syncwarp();

    const int h0 = 2 * lane;
    const float sa = g_sattr[n];
    const float dg = (float)cnt;
    float o0 = sa * g_c1[l][h0 + 0] + dg * g_c2[l][h0 + 0] + nb[l * HID + h0 + 0];
    float o1 = sa * g_c1[l][h0 + 1] + dg * g_c2[l][h0 + 1] + nb[l * HID + h0 + 1];
#pragma unroll
    for (int k = 0; k < HID; k++) {
        float a = sA[warp][k];          // broadcast
        o0 += a * sW[k][h0 + 0];
        o1 += a * sW[k][h0 + 1];
    }
    // ReLU (subsequent LeakyReLU is identity on non-negative values)
    o0 = fmaxf(o0, 0.f);
    o1 = fmaxf(o1, 0.f);
    xout[n * HID + h0 + 0] = o0;
    xout[n * HID + h0 + 1] = o1;
}

// ---------------- pooling: per-node dot with fc_w, segment into graphs ----------------
__global__ void k_pool(const float* __restrict__ x, const float* __restrict__ fcw,
                       const int* __restrict__ batch) {
    int gt = blockIdx.x * blockDim.x + threadIdx.x;
    int n = gt >> 5;
    int lane = gt & 31;
    if (n >= N_NODES) return;
    const float2* __restrict__ x2 = (const float2*)x;
    float2 w = ((const float2*)fcw)[lane];
    float2 v = x2[n * 32 + lane];
    float s = v.x * w.x + v.y * w.y;
#pragma unroll
    for (int off = 16; off; off >>= 1) s += __shfl_down_sync(0xffffffffu, s, off);
    if (lane == 0) {
        int g = batch[n];
        atomicAdd(&g_gsum[g], s);
        atomicAdd(&g_gcnt[g], 1);
    }
}

// ---------------- final: mean + bias ----------------
__global__ void k_out(float* __restrict__ out, const float* __restrict__ fcb) {
    int g = threadIdx.x;
    if (g < N_GRAPHS) {
        float c = (float)g_gcnt[g];
        out[g] = g_gsum[g] / fmaxf(c, 1.f) + fcb[0];
    }
}

// ---------------- launch ----------------
extern "C" void kernel_launch(void* const* d_in, const int* in_sizes, int n_in,
                              void* d_out, int out_size) {
    const float* x    = (const float*)d_in[0];
    const float* ea   = (const float*)d_in[1];
    const float* ew   = (const float*)d_in[2];
    const float* eb   = (const float*)d_in[3];
    const float* nw   = (const float*)d_in[4];
    const float* nb   = (const float*)d_in[5];
    const float* fcw  = (const float*)d_in[6];
    const float* fcb  = (const float*)d_in[7];
    const int*   ei   = (const int*)d_in[8];
    const int*   batch= (const int*)d_in[9];
    float* out = (float*)d_out;

    const int EB = (N_EDGES + 255) / 256;
    const int NB = (N_NODES + 255) / 256;

    k_init<<<NB, 256>>>();
    k_edge1<<<EB, 256>>>(ei, ea);
    k_const<<<1, 256>>>(ew, eb, nw);
    k_scan<<<1, 1024>>>();
    k_edge2<<<EB, 256>>>(ei);

    float* b0; cudaGetSymbolAddress((void**)&b0, g_buf0);
    float* b1; cudaGetSymbolAddress((void**)&b1, g_buf1);

    const int LB = (N_NODES + 7) / 8;
    k_layer<<<LB, 256>>>(x,  b0, nw, nb, 0);
    k_layer<<<LB, 256>>>(b0, b1, nw, nb, 1);
    k_layer<<<LB, 256>>>(b1, b0, nw, nb, 2);

    k_pool<<<(N_NODES * 32 + 255) / 256, 256>>>(b0, fcw, batch);
    k_out<<<1, N_GRAPHS>>>(out, fcb);
}

// round 2
// speedup vs baseline: 1.3540x; 1.3540x over previous
#include <cuda_runtime.h>

#define N_NODES 50000
#define N_EDGES 800000
#define HID 64
#define N_LAYERS 3
#define N_GRAPHS 64
#define NB_NODES 196   // ceil(50000/256)

// ---------------- scratch (device globals; no allocation allowed) ----------------
__device__ float g_buf0[N_NODES * HID];
__device__ float g_buf1[N_NODES * HID];
__device__ int   g_deg[N_NODES];
__device__ int   g_rowptr[N_NODES];
__device__ int   g_fill[N_NODES];
__device__ int   g_part[256];
__device__ int   g_perm[N_EDGES];
__device__ float g_sattr[N_NODES];
__device__ float g_c1[N_LAYERS][HID];
__device__ float g_c2[N_LAYERS][HID];
__device__ float g_gsum[N_GRAPHS];

// ---------------- pre: zero scratch + rank-2 layer constants ----------------
// blocks [0, NB_NODES): init.  block NB_NODES: c1 = edge_w@W2, c2 = edge_b@W2.
__global__ void k_pre(const float* __restrict__ ew, const float* __restrict__ eb,
                      const float* __restrict__ nw) {
    if (blockIdx.x < NB_NODES) {
        int i = blockIdx.x * 256 + threadIdx.x;
        if (i < N_NODES) { g_deg[i] = 0; g_sattr[i] = 0.f; }
        if (i < N_GRAPHS) g_gsum[i] = 0.f;
    } else {
        int tid = threadIdx.x;
        if (tid >= N_LAYERS * HID) return;
        int l = tid / HID, h = tid % HID;
        float a = 0.f, b = 0.f;
        for (int k = 0; k < HID; k++) {
            float w = nw[(l * 2 * HID + HID + k) * HID + h];  // W2[k][h]
            a += ew[l * HID + k] * w;
            b += eb[l * HID + k] * w;
        }
        g_c1[l][h] = a;
        g_c2[l][h] = b;
    }
}

// ---------------- edge pass 1: in-degree + scalar edge_attr segment sum ----------------
__global__ void k_edge1(const int* __restrict__ ei, const float* __restrict__ ea) {
    int e = blockIdx.x * blockDim.x + threadIdx.x;
    if (e >= N_EDGES) return;
    int d = ei[N_EDGES + e];
    atomicAdd(&g_deg[d], 1);
    atomicAdd(&g_sattr[d], ea[e]);
}

// ---------------- scan A: per-block partial sums of deg ----------------
__global__ void k_scanA() {
    __shared__ int sW[8];
    int i = blockIdx.x * 256 + threadIdx.x;
    int v = (i < N_NODES) ? g_deg[i] : 0;
#pragma unroll
    for (int o = 16; o; o >>= 1) v += __shfl_down_sync(0xffffffffu, v, o);
    if ((threadIdx.x & 31) == 0) sW[threadIdx.x >> 5] = v;
    __syncthreads();
    if (threadIdx.x == 0) {
        int t = 0;
#pragma unroll
        for (int w = 0; w < 8; w++) t += sW[w];
        g_part[blockIdx.x] = t;
    }
}

// ---------------- scan C: per-block exclusive scan + base from partials ----------------
__global__ void k_scanC() {
    __shared__ int sW[8];
    __shared__ int sBase;
    const int b = blockIdx.x, tid = threadIdx.x;
    const int lane = tid & 31, w = tid >> 5;

    // base = sum of partials before this block (redundant per-block, cheap)
    int s = 0;
    for (int j = tid; j < b; j += 256) s += g_part[j];
#pragma unroll
    for (int o = 16; o; o >>= 1) s += __shfl_down_sync(0xffffffffu, s, o);
    if (lane == 0) sW[w] = s;
    __syncthreads();
    if (tid == 0) {
        int t = 0;
#pragma unroll
        for (int j = 0; j < 8; j++) t += sW[j];
        sBase = t;
    }
    __syncthreads();
    const int base = sBase;
    __syncthreads();

    // in-block exclusive scan of deg
    int i = b * 256 + tid;
    int v = (i < N_NODES) ? g_deg[i] : 0;
    int inc = v;
#pragma unroll
    for (int o = 1; o < 32; o <<= 1) {
        int t = __shfl_up_sync(0xffffffffu, inc, o);
        if (lane >= o) inc += t;
    }
    if (lane == 31) sW[w] = inc;
    __syncthreads();
    int wo = 0;
    for (int j = 0; j < w; j++) wo += sW[j];
    int exc = base + wo + inc - v;
    if (i < N_NODES) { g_rowptr[i] = exc; g_fill[i] = exc; }
}

// ---------------- edge pass 2: bucket-place src into CSR order ----------------
__global__ void k_edge2(const int* __restrict__ ei) {
    int e = blockIdx.x * blockDim.x + threadIdx.x;
    if (e >= N_EDGES) return;
    int s = ei[e];
    int d = ei[N_EDGES + e];
    int pos = atomicAdd(&g_fill[d], 1);
    g_perm[pos] = s;
}

// ---------------- fused layer: CSR gather-sum + node MLP + ReLU (+pool on last) ----------------
__global__ void __launch_bounds__(256) k_layer(
    const float* __restrict__ xin, float* __restrict__ xout,
    const float* __restrict__ nw, const float* __restrict__ nb, int l,
    int last, const float* __restrict__ fcw, const int* __restrict__ batch)
{
    __shared__ float sW[HID][HID + 2];
    __shared__ float sA[8][HID];
    const int tid = threadIdx.x;

    for (int i = tid; i < HID * HID; i += 256) {
        int k = i / HID, h = i % HID;
        sW[k][h] = nw[(l * 2 * HID + k) * HID + h];
    }
    __syncthreads();

    const int warp = tid >> 5, lane = tid & 31;
    const int n = blockIdx.x * 8 + warp;
    if (n >= N_NODES) return;

    const int beg = g_rowptr[n];
    const int cnt = g_deg[n];

    // two half-warps process interleaved edges; float4 loads (16 lanes cover a row)
    const float4* __restrict__ x4 = (const float4*)xin;
    const int c = lane & 15, g = lane >> 4;
    float4 a0 = {0,0,0,0}, a1 = {0,0,0,0}, a2 = {0,0,0,0}, a3 = {0,0,0,0};
    int i = g;
    for (; i + 6 < cnt; i += 8) {
        int s0 = g_perm[beg + i + 0];
        int s1 = g_perm[beg + i + 2];
        int s2 = g_perm[beg + i + 4];
        int s3 = g_perm[beg + i + 6];
        float4 v0 = x4[s0 * 16 + c];
        float4 v1 = x4[s1 * 16 + c];
        float4 v2 = x4[s2 * 16 + c];
        float4 v3 = x4[s3 * 16 + c];
        a0.x += v0.x; a0.y += v0.y; a0.z += v0.z; a0.w += v0.w;
        a1.x += v1.x; a1.y += v1.y; a1.z += v1.z; a1.w += v1.w;
        a2.x += v2.x; a2.y += v2.y; a2.z += v2.z; a2.w += v2.w;
        a3.x += v3.x; a3.y += v3.y; a3.z += v3.z; a3.w += v3.w;
    }
    for (; i < cnt; i += 2) {
        float4 v = x4[g_perm[beg + i] * 16 + c];
        a0.x += v.x; a0.y += v.y; a0.z += v.z; a0.w += v.w;
    }
    float ax = a0.x + a1.x + a2.x + a3.x;
    float ay = a0.y + a1.y + a2.y + a3.y;
    float az = a0.z + a1.z + a2.z + a3.z;
    float aw = a0.w + a1.w + a2.w + a3.w;
    // combine the two half-warp partial sums
    ax += __shfl_xor_sync(0xffffffffu, ax, 16);
    ay += __shfl_xor_sync(0xffffffffu, ay, 16);
    az += __shfl_xor_sync(0xffffffffu, az, 16);
    aw += __shfl_xor_sync(0xffffffffu, aw, 16);
    if (g == 0) {
        sA[warp][4 * c + 0] = ax;
        sA[warp][4 * c + 1] = ay;
        sA[warp][4 * c + 2] = az;
        sA[warp][4 * c + 3] = aw;
    }
    __syncwarp();

    const int h0 = 2 * lane;
    const float sa = g_sattr[n];
    const float dg = (float)cnt;
    float o0 = sa * g_c1[l][h0 + 0] + dg * g_c2[l][h0 + 0] + nb[l * HID + h0 + 0];
    float o1 = sa * g_c1[l][h0 + 1] + dg * g_c2[l][h0 + 1] + nb[l * HID + h0 + 1];
#pragma unroll
    for (int k = 0; k < HID; k++) {
        float a = sA[warp][k];
        o0 += a * sW[k][h0 + 0];
        o1 += a * sW[k][h0 + 1];
    }
    o0 = fmaxf(o0, 0.f);  // ReLU; LeakyReLU is identity on >=0
    o1 = fmaxf(o1, 0.f);

    if (!last) {
        ((float2*)xout)[n * 32 + lane] = make_float2(o0, o1);
    } else {
        // fused global_mean_pool numerator + fc: per-node dot with fc_w
        float2 w2 = ((const float2*)fcw)[lane];
        float s = o0 * w2.x + o1 * w2.y;
#pragma unroll
        for (int off = 16; off; off >>= 1) s += __shfl_down_sync(0xffffffffu, s, off);
        if (lane == 0) atomicAdd(&g_gsum[batch[n]], s);
    }
}

// ---------------- final: counts via binary search on sorted batch, mean + bias ----------------
__global__ void k_out(float* __restrict__ out, const float* __restrict__ fcb,
                      const int* __restrict__ batch) {
    int g = threadIdx.x;
    if (g >= N_GRAPHS) return;
    int lo = 0, hi = N_NODES;
    while (lo < hi) { int m = (lo + hi) >> 1; if (batch[m] < g) lo = m + 1; else hi = m; }
    int lo2 = lo, hi2 = N_NODES;
    while (lo2 < hi2) { int m = (lo2 + hi2) >> 1; if (batch[m] < g + 1) lo2 = m + 1; else hi2 = m; }
    float c = (float)(lo2 - lo);
    out[g] = g_gsum[g] / fmaxf(c, 1.f) + fcb[0];
}

// ---------------- launch ----------------
extern "C" void kernel_launch(void* const* d_in, const int* in_sizes, int n_in,
                              void* d_out, int out_size) {
    const float* x    = (const float*)d_in[0];
    const float* ea   = (const float*)d_in[1];
    const float* ew   = (const float*)d_in[2];
    const float* eb   = (const float*)d_in[3];
    const float* nw   = (const float*)d_in[4];
    const float* nb   = (const float*)d_in[5];
    const float* fcw  = (const float*)d_in[6];
    const float* fcb  = (const float*)d_in[7];
    const int*   ei   = (const int*)d_in[8];
    const int*   batch= (const int*)d_in[9];
    float* out = (float*)d_out;

    const int EB = (N_EDGES + 255) / 256;

    float* b0; cudaGetSymbolAddress((void**)&b0, g_buf0);
    float* b1; cudaGetSymbolAddress((void**)&b1, g_buf1);

    k_pre  <<<NB_NODES + 1, 256>>>(ew, eb, nw);
    k_edge1<<<EB, 256>>>(ei, ea);
    k_scanA<<<NB_NODES, 256>>>();
    k_scanC<<<NB_NODES, 256>>>();
    k_edge2<<<EB, 256>>>(ei);

    const int LB = (N_NODES + 7) / 8;
    k_layer<<<LB, 256>>>(x,  b0, nw, nb, 0, 0, fcw, batch);   // launch #6 -> profiled
    k_layer<<<LB, 256>>>(b0, b1, nw, nb, 1, 0, fcw, batch);
    k_layer<<<LB, 256>>>(b1, b0, nw, nb, 2, 1, fcw, batch);   // fused pooling

    k_out<<<1, N_GRAPHS>>>(out, fcb, batch);
}

// round 3
// speedup vs baseline: 1.3984x; 1.0328x over previous
#include <cuda_runtime.h>

#define N_NODES 50000
#define N_EDGES 800000
#define HID 64
#define N_LAYERS 3
#define N_GRAPHS 64
#define NB_NODES 196   // ceil(50000/256)

// ---------------- scratch (device globals; zero-initialized at module load) ----------------
__device__ float g_buf0[N_NODES * HID];
__device__ float g_buf1[N_NODES * HID];
__device__ int   g_deg[N_NODES];      // must be zero at call entry (cleanup restores)
__device__ int   g_rowptr[N_NODES];
__device__ int   g_fill[N_NODES];
__device__ int   g_perm[N_EDGES];
__device__ float g_sattr[N_NODES];    // must be zero at call entry (cleanup restores)
__device__ float g_c1[N_LAYERS][HID];
__device__ float g_c2[N_LAYERS][HID];
__device__ float g_gsum[N_GRAPHS];    // zeroed in k_scan1 each call

// ---------------- edge pass 1: in-degree + scalar edge_attr segment sum (2 edges/thread) ----------------
__global__ void k_edge1(const int* __restrict__ ei, const float* __restrict__ ea) {
    int p = blockIdx.x * blockDim.x + threadIdx.x;   // pair index
    int e = p * 2;
    if (e >= N_EDGES) return;
    int2   d2 = *(const int2*)  (ei + N_EDGES + e);
    float2 a2 = *(const float2*)(ea + e);
    atomicAdd(&g_deg[d2.x], 1);
    atomicAdd(&g_sattr[d2.x], a2.x);
    atomicAdd(&g_deg[d2.y], 1);
    atomicAdd(&g_sattr[d2.y], a2.y);
}

// ---------------- single-kernel scan: each block redundantly sums its prefix ----------------
// blocks [0, NB_NODES): exclusive scan of deg -> rowptr, fill
// block NB_NODES: rank-2 constants c1/c2 + zero g_gsum
__global__ void __launch_bounds__(256) k_scan1(const float* __restrict__ ew,
                                               const float* __restrict__ eb,
                                               const float* __restrict__ nw) {
    const int b = blockIdx.x, tid = threadIdx.x;
    if (b == NB_NODES) {
        if (tid < N_GRAPHS) g_gsum[tid] = 0.f;
        if (tid >= N_LAYERS * HID) return;
        int l = tid / HID, h = tid % HID;
        float a = 0.f, c = 0.f;
        for (int k = 0; k < HID; k++) {
            float w = nw[(l * 2 * HID + HID + k) * HID + h];  // W2[k][h]
            a += ew[l * HID + k] * w;
            c += eb[l * HID + k] * w;
        }
        g_c1[l][h] = a;
        g_c2[l][h] = c;
        return;
    }

    __shared__ int sW[8];
    __shared__ int sBase;
    const int lane = tid & 31, w = tid >> 5;

    // base = sum of deg[0 .. b*256) via int4 strided reads
    const int4* __restrict__ d4 = (const int4*)g_deg;
    const int nq = b * 64;           // int4 count in prefix
    int s = 0;
    for (int j = tid; j < nq; j += 256) {
        int4 v = d4[j];
        s += v.x + v.y + v.z + v.w;
    }
#pragma unroll
    for (int o = 16; o; o >>= 1) s += __shfl_down_sync(0xffffffffu, s, o);
    if (lane == 0) sW[w] = s;
    __syncthreads();
    if (tid == 0) {
        int t = 0;
#pragma unroll
        for (int j = 0; j < 8; j++) t += sW[j];
        sBase = t;
    }
    __syncthreads();
    const int base = sBase;
    __syncthreads();

    // in-block exclusive scan of own chunk
    int i = b * 256 + tid;
    int v = (i < N_NODES) ? g_deg[i] : 0;
    int inc = v;
#pragma unroll
    for (int o = 1; o < 32; o <<= 1) {
        int t = __shfl_up_sync(0xffffffffu, inc, o);
        if (lane >= o) inc += t;
    }
    if (lane == 31) sW[w] = inc;
    __syncthreads();
    int wo = 0;
    for (int j = 0; j < w; j++) wo += sW[j];
    int exc = base + wo + inc - v;
    if (i < N_NODES) { g_rowptr[i] = exc; g_fill[i] = exc; }
}

// ---------------- edge pass 2: bucket-place src into CSR order (2 edges/thread) ----------------
__global__ void k_edge2(const int* __restrict__ ei) {
    int p = blockIdx.x * blockDim.x + threadIdx.x;
    int e = p * 2;
    if (e >= N_EDGES) return;
    int2 s2 = *(const int2*)(ei + e);
    int2 d2 = *(const int2*)(ei + N_EDGES + e);
    int pos0 = atomicAdd(&g_fill[d2.x], 1);
    g_perm[pos0] = s2.x;
    int pos1 = atomicAdd(&g_fill[d2.y], 1);
    g_perm[pos1] = s2.y;
}

// ---------------- fused layer: CSR gather-sum + node MLP + ReLU (+pool on last) ----------------
__global__ void __launch_bounds__(256) k_layer(
    const float* __restrict__ xin, float* __restrict__ xout,
    const float* __restrict__ nw, const float* __restrict__ nb, int l,
    int last, const float* __restrict__ fcw, const int* __restrict__ batch)
{
    __shared__ float2 sW2[HID][32];   // sW2[k][j] = (W1[k][2j], W1[k][2j+1])
    __shared__ float  sA[8][HID];
    const int tid = threadIdx.x;

    // stage W1 as float2 pairs
    {
        const float2* __restrict__ nw2 = (const float2*)(nw + (size_t)l * 2 * HID * HID);
        for (int i = tid; i < HID * 32; i += 256) {
            int k = i >> 5, j = i & 31;
            sW2[k][j] = nw2[k * 32 + j];
        }
    }
    __syncthreads();

    const int warp = tid >> 5, lane = tid & 31;
    const int n = blockIdx.x * 8 + warp;   // grid covers exactly N_NODES

    const int beg = g_rowptr[n];
    const int cnt = g_deg[n];

    // two half-warps; 4 independent predicated loads per round, no serial tail
    const float4* __restrict__ x4 = (const float4*)xin;
    const int c = lane & 15, g = lane >> 4;
    float4 a0 = {0,0,0,0}, a1 = {0,0,0,0}, a2 = {0,0,0,0}, a3 = {0,0,0,0};
    for (int i0 = 4 * g; i0 < cnt; i0 += 8) {
        const int* __restrict__ pp = g_perm + beg + i0;
        int rem = cnt - i0;           // >= 1
        if (rem >= 4) {
            int s0 = pp[0], s1 = pp[1], s2 = pp[2], s3 = pp[3];
            float4 v0 = x4[s0 * 16 + c];
            float4 v1 = x4[s1 * 16 + c];
            float4 v2 = x4[s2 * 16 + c];
            float4 v3 = x4[s3 * 16 + c];
            a0.x += v0.x; a0.y += v0.y; a0.z += v0.z; a0.w += v0.w;
            a1.x += v1.x; a1.y += v1.y; a1.z += v1.z; a1.w += v1.w;
            a2.x += v2.x; a2.y += v2.y; a2.z += v2.z; a2.w += v2.w;
            a3.x += v3.x; a3.y += v3.y; a3.z += v3.z; a3.w += v3.w;
        } else {
            int s0 = pp[0];
            int s1 = (rem > 1) ? pp[1] : s0;
            int s2 = (rem > 2) ? pp[2] : s0;
            float4 v0 = x4[s0 * 16 + c];
            a0.x += v0.x; a0.y += v0.y; a0.z += v0.z; a0.w += v0.w;
            if (rem > 1) {
                float4 v1 = x4[s1 * 16 + c];
                a1.x += v1.x; a1.y += v1.y; a1.z += v1.z; a1.w += v1.w;
            }
            if (rem > 2) {
                float4 v2 = x4[s2 * 16 + c];
                a2.x += v2.x; a2.y += v2.y; a2.z += v2.z; a2.w += v2.w;
            }
        }
    }
    float ax = a0.x + a1.x + a2.x + a3.x;
    float ay = a0.y + a1.y + a2.y + a3.y;
    float az = a0.z + a1.z + a2.z + a3.z;
    float aw = a0.w + a1.w + a2.w + a3.w;
    ax += __shfl_xor_sync(0xffffffffu, ax, 16);
    ay += __shfl_xor_sync(0xffffffffu, ay, 16);
    az += __shfl_xor_sync(0xffffffffu, az, 16);
    aw += __shfl_xor_sync(0xffffffffu, aw, 16);
    if (g == 0) {
        sA[warp][4 * c + 0] = ax;
        sA[warp][4 * c + 1] = ay;
        sA[warp][4 * c + 2] = az;
        sA[warp][4 * c + 3] = aw;
    }
    __syncwarp();

    const int h0 = 2 * lane;
    const float sa = g_sattr[n];
    const float dg = (float)cnt;
    float o0 = sa * g_c1[l][h0 + 0] + dg * g_c2[l][h0 + 0] + nb[l * HID + h0 + 0];
    float o1 = sa * g_c1[l][h0 + 1] + dg * g_c2[l][h0 + 1] + nb[l * HID + h0 + 1];
#pragma unroll
    for (int k = 0; k < HID; k++) {
        float  a = sA[warp][k];      // broadcast
        float2 w = sW2[k][lane];     // conflict-free LDS.64
        o0 += a * w.x;
        o1 += a * w.y;
    }
    o0 = fmaxf(o0, 0.f);   // ReLU; LeakyReLU identity on >= 0
    o1 = fmaxf(o1, 0.f);

    if (!last) {
        ((float2*)xout)[n * 32 + lane] = make_float2(o0, o1);
    } else {
        float2 w2 = ((const float2*)fcw)[lane];
        float s = o0 * w2.x + o1 * w2.y;
#pragma unroll
        for (int off = 16; off; off >>= 1) s += __shfl_down_sync(0xffffffffu, s, off);
        if (lane == 0) atomicAdd(&g_gsum[batch[n]], s);
    }
}

// ---------------- final: counts via binary search on sorted batch, mean + bias ----------------
__global__ void k_out(float* __restrict__ out, const float* __restrict__ fcb,
                      const int* __restrict__ batch) {
    int g = threadIdx.x;
    if (g >= N_GRAPHS) return;
    int lo = 0, hi = N_NODES;
    while (lo < hi) { int m = (lo + hi) >> 1; if (batch[m] < g) lo = m + 1; else hi = m; }
    int lo2 = lo, hi2 = N_NODES;
    while (lo2 < hi2) { int m = (lo2 + hi2) >> 1; if (batch[m] < g + 1) lo2 = m + 1; else hi2 = m; }
    float c = (float)(lo2 - lo);
    out[g] = g_gsum[g] / fmaxf(c, 1.f) + fcb[0];
}

// ---------------- cleanup: restore zero invariant for next call ----------------
__global__ void k_cleanup() {
    int i = blockIdx.x * 256 + threadIdx.x;
    if (i < N_NODES) { g_deg[i] = 0; g_sattr[i] = 0.f; }
}

// ---------------- launch ----------------
extern "C" void kernel_launch(void* const* d_in, const int* in_sizes, int n_in,
                              void* d_out, int out_size) {
    const float* x    = (const float*)d_in[0];
    const float* ea   = (const float*)d_in[1];
    const float* ew   = (const float*)d_in[2];
    const float* eb   = (const float*)d_in[3];
    const float* nw   = (const float*)d_in[4];
    const float* nb   = (const float*)d_in[5];
    const float* fcw  = (const float*)d_in[6];
    const float* fcb  = (const float*)d_in[7];
    const int*   ei   = (const int*)d_in[8];
    const int*   batch= (const int*)d_in[9];
    float* out = (float*)d_out;

    const int EB2 = (N_EDGES / 2 + 255) / 256;

    float* b0; cudaGetSymbolAddress((void**)&b0, g_buf0);
    float* b1; cudaGetSymbolAddress((void**)&b1, g_buf1);

    k_edge1<<<EB2, 256>>>(ei, ea);                 // #1
    k_scan1<<<NB_NODES + 1, 256>>>(ew, eb, nw);    // #2 (scan + consts + gsum zero)
    k_edge2<<<EB2, 256>>>(ei);                     // #3

    const int LB = N_NODES / 8;                    // 6250, exact
    k_layer<<<LB, 256>>>(x,  b0, nw, nb, 0, 0, fcw, batch);   // #4 -> profiled
    k_layer<<<LB, 256>>>(b0, b1, nw, nb, 1, 0, fcw, batch);   // #5
    k_layer<<<LB, 256>>>(b1, b0, nw, nb, 2, 1, fcw, batch);   // #6 fused pooling

    k_out<<<1, N_GRAPHS>>>(out, fcb, batch);       // #7
    k_cleanup<<<NB_NODES, 256>>>();                // #8 restore zeros
}

// round 4
// speedup vs baseline: 1.5042x; 1.0757x over previous
#include <cuda_runtime.h>
#include <cuda_fp16.h>

#define N_NODES 50000
#define N_EDGES 800000
#define HID 64
#define N_LAYERS 3
#define N_GRAPHS 64
#define NB_NODES 196        // ceil(50000/256)
#define EB2 1563            // ceil(800000/2/256)
#define CVB 6250            // N_NODES*32 float2 / 256

// ---------------- scratch (device globals; zero-initialized at module load) ----------------
__device__ __half g_xh[N_NODES * HID];   // fp16 copy of input features
__device__ __half g_h0[N_NODES * HID];
__device__ __half g_h1[N_NODES * HID];
__device__ int    g_deg[N_NODES];        // zero at entry (k_out restores)
__device__ int    g_rowptr[N_NODES];
__device__ int    g_fill[N_NODES];
__device__ int    g_perm[N_EDGES];
__device__ float  g_sattr[N_NODES];      // zero at entry (k_out restores)
__device__ float  g_c1[N_LAYERS][HID];
__device__ float  g_c2[N_LAYERS][HID];
__device__ float  g_gsum[N_GRAPHS];      // zeroed in k_scan1

// ---------------- #1: edge pass 1 (deg + sattr) fused with fp32->fp16 convert ----------------
__global__ void k_pre(const int* __restrict__ ei, const float* __restrict__ ea,
                      const float* __restrict__ x) {
    if (blockIdx.x < EB2) {
        int p = blockIdx.x * 256 + threadIdx.x;
        int e = p * 2;
        if (e >= N_EDGES) return;
        int2   d2 = *(const int2*)  (ei + N_EDGES + e);
        float2 a2 = *(const float2*)(ea + e);
        atomicAdd(&g_deg[d2.x], 1);
        atomicAdd(&g_sattr[d2.x], a2.x);
        atomicAdd(&g_deg[d2.y], 1);
        atomicAdd(&g_sattr[d2.y], a2.y);
    } else {
        int i = (blockIdx.x - EB2) * 256 + threadIdx.x;   // float2 index
        if (i < N_NODES * 32) {
            float2 v = ((const float2*)x)[i];
            ((__half2*)g_xh)[i] = __floats2half2_rn(v.x, v.y);
        }
    }
}

// ---------------- #2: scan (redundant-prefix) + rank-2 constants + gsum zero ----------------
__global__ void __launch_bounds__(256) k_scan1(const float* __restrict__ ew,
                                               const float* __restrict__ eb,
                                               const float* __restrict__ nw) {
    const int b = blockIdx.x, tid = threadIdx.x;
    if (b == NB_NODES) {
        if (tid < N_GRAPHS) g_gsum[tid] = 0.f;
        if (tid >= N_LAYERS * HID) return;
        int l = tid / HID, h = tid % HID;
        float a = 0.f, c = 0.f;
        for (int k = 0; k < HID; k++) {
            float w = nw[(l * 2 * HID + HID + k) * HID + h];  // W2[k][h]
            a += ew[l * HID + k] * w;
            c += eb[l * HID + k] * w;
        }
        g_c1[l][h] = a;
        g_c2[l][h] = c;
        return;
    }

    __shared__ int sW[8];
    __shared__ int sBase;
    const int lane = tid & 31, w = tid >> 5;

    const int4* __restrict__ d4 = (const int4*)g_deg;
    const int nq = b * 64;
    int s = 0;
    for (int j = tid; j < nq; j += 256) {
        int4 v = d4[j];
        s += v.x + v.y + v.z + v.w;
    }
#pragma unroll
    for (int o = 16; o; o >>= 1) s += __shfl_down_sync(0xffffffffu, s, o);
    if (lane == 0) sW[w] = s;
    __syncthreads();
    if (tid == 0) {
        int t = 0;
#pragma unroll
        for (int j = 0; j < 8; j++) t += sW[j];
        sBase = t;
    }
    __syncthreads();
    const int base = sBase;
    __syncthreads();

    int i = b * 256 + tid;
    int v = (i < N_NODES) ? g_deg[i] : 0;
    int inc = v;
#pragma unroll
    for (int o = 1; o < 32; o <<= 1) {
        int t = __shfl_up_sync(0xffffffffu, inc, o);
        if (lane >= o) inc += t;
    }
    if (lane == 31) sW[w] = inc;
    __syncthreads();
    int wo = 0;
    for (int j = 0; j < w; j++) wo += sW[j];
    int exc = base + wo + inc - v;
    if (i < N_NODES) { g_rowptr[i] = exc; g_fill[i] = exc; }
}

// ---------------- #3: edge pass 2: CSR bucket placement ----------------
__global__ void k_edge2(const int* __restrict__ ei) {
    int p = blockIdx.x * blockDim.x + threadIdx.x;
    int e = p * 2;
    if (e >= N_EDGES) return;
    int2 s2 = *(const int2*)(ei + e);
    int2 d2 = *(const int2*)(ei + N_EDGES + e);
    int pos0 = atomicAdd(&g_fill[d2.x], 1);
    g_perm[pos0] = s2.x;
    int pos1 = atomicAdd(&g_fill[d2.y], 1);
    g_perm[pos1] = s2.y;
}

// ---------------- #4-6: fused layer: gather (fp16) + MLP (8 nodes/warp) + ReLU (+pool) ----------------
__global__ void __launch_bounds__(256) k_layer(
    const __half* __restrict__ xin, __half* __restrict__ xout,
    const float* __restrict__ nw, const float* __restrict__ nb, int l,
    int last, const float* __restrict__ fcw, const int* __restrict__ batch)
{
    __shared__ float2 sW2[HID][32];     // sW2[k][j] = (W1[k][2j], W1[k][2j+1])  16KB
    __shared__ float  sA[8][8][HID];    // [warp][node j][k]                      16KB
    const int tid = threadIdx.x;

    {
        const float2* __restrict__ nw2 = (const float2*)(nw + (size_t)l * 2 * HID * HID);
        for (int i = tid; i < HID * 32; i += 256) {
            int k = i >> 5, j = i & 31;
            sW2[k][j] = nw2[k * 32 + j];
        }
    }
    __syncthreads();

    const int warp = tid >> 5, lane = tid & 31;
    const int nbase = blockIdx.x * 64 + warp * 8;

    const float2 c1v = ((const float2*)g_c1[l])[lane];
    const float2 c2v = ((const float2*)g_c2[l])[lane];
    const float2 bv  = ((const float2*)(nb + l * HID))[lane];
    const __half2* __restrict__ xh2 = (const __half2*)xin;

    // ---- gather: 8 nodes per warp, whole warp covers one 128B row per edge ----
#pragma unroll
    for (int j = 0; j < 8; j++) {
        const int n = nbase + j;
        int beg = 0, cnt = 0;
        if (n < N_NODES) { beg = g_rowptr[n]; cnt = g_deg[n]; }
        float ax0 = 0.f, ay0 = 0.f, ax1 = 0.f, ay1 = 0.f;
        float ax2 = 0.f, ay2 = 0.f, ax3 = 0.f, ay3 = 0.f;
        for (int i = 0; i < cnt; i += 4) {
            const int* __restrict__ pp = g_perm + beg + i;
            const int rem = cnt - i;
            int s0 = pp[0];
            int s1 = (rem > 1) ? pp[1] : s0;
            int s2 = (rem > 2) ? pp[2] : s0;
            int s3 = (rem > 3) ? pp[3] : s0;
            float2 v0 = __half22float2(xh2[s0 * 32 + lane]);
            float2 v1 = __half22float2(xh2[s1 * 32 + lane]);
            float2 v2 = __half22float2(xh2[s2 * 32 + lane]);
            float2 v3 = __half22float2(xh2[s3 * 32 + lane]);
            ax0 += v0.x; ay0 += v0.y;
            if (rem > 1) { ax1 += v1.x; ay1 += v1.y; }
            if (rem > 2) { ax2 += v2.x; ay2 += v2.y; }
            if (rem > 3) { ax3 += v3.x; ay3 += v3.y; }
        }
        float ax = (ax0 + ax1) + (ax2 + ax3);
        float ay = (ay0 + ay1) + (ay2 + ay3);
        ((float2*)sA[warp][j])[lane] = make_float2(ax, ay);   // A[j][2lane], A[j][2lane+1]
    }
    __syncwarp();

    // ---- MLP: weights fetched once per warp per k-block, reused for 8 nodes ----
    float o0[8], o1[8];
#pragma unroll
    for (int j = 0; j < 8; j++) { o0[j] = 0.f; o1[j] = 0.f; }

#pragma unroll
    for (int kk = 0; kk < 16; kk++) {
        const float2 w0 = sW2[4 * kk + 0][lane];
        const float2 w1 = sW2[4 * kk + 1][lane];
        const float2 w2 = sW2[4 * kk + 2][lane];
        const float2 w3 = sW2[4 * kk + 3][lane];
#pragma unroll
        for (int j = 0; j < 8; j++) {
            const float4 a = ((const float4*)sA[warp][j])[kk];  // broadcast, 1 phase
            o0[j] += a.x * w0.x + a.y * w1.x + a.z * w2.x + a.w * w3.x;
            o1[j] += a.x * w0.y + a.y * w1.y + a.z * w2.y + a.w * w3.y;
        }
    }

    // ---- epilogue: rank-2 edge part + bias + ReLU, write fp16 (or pool on last) ----
    const float2 fw = last ? ((const float2*)fcw)[lane] : make_float2(0.f, 0.f);
#pragma unroll
    for (int j = 0; j < 8; j++) {
        const int n = nbase + j;
        if (n >= N_NODES) break;
        const float sa = g_sattr[n];
        const float dg = (float)g_deg[n];
        float u0 = o0[j] + sa * c1v.x + dg * c2v.x + bv.x;
        float u1 = o1[j] + sa * c1v.y + dg * c2v.y + bv.y;
        u0 = fmaxf(u0, 0.f);   // ReLU; LeakyReLU identity on >= 0
        u1 = fmaxf(u1, 0.f);
        if (!last) {
            ((__half2*)xout)[n * 32 + lane] = __floats2half2_rn(u0, u1);
        } else {
            float s = u0 * fw.x + u1 * fw.y;
#pragma unroll
            for (int off = 16; off; off >>= 1) s += __shfl_down_sync(0xffffffffu, s, off);
            if (lane == 0) atomicAdd(&g_gsum[batch[n]], s);
        }
    }
}

// ---------------- #7: final output (block 0) + scratch cleanup (blocks 1..) ----------------
__global__ void k_out(float* __restrict__ out, const float* __restrict__ fcb,
                      const int* __restrict__ batch) {
    if (blockIdx.x == 0) {
        int g = threadIdx.x;
        if (g >= N_GRAPHS) return;
        int lo = 0, hi = N_NODES;
        while (lo < hi) { int m = (lo + hi) >> 1; if (batch[m] < g) lo = m + 1; else hi = m; }
        int lo2 = lo, hi2 = N_NODES;
        while (lo2 < hi2) { int m = (lo2 + hi2) >> 1; if (batch[m] < g + 1) lo2 = m + 1; else hi2 = m; }
        float c = (float)(lo2 - lo);
        out[g] = g_gsum[g] / fmaxf(c, 1.f) + fcb[0];
    } else {
        int i = (blockIdx.x - 1) * 256 + threadIdx.x;
        if (i < N_NODES) { g_deg[i] = 0; g_sattr[i] = 0.f; }
    }
}

// ---------------- launch ----------------
extern "C" void kernel_launch(void* const* d_in, const int* in_sizes, int n_in,
                              void* d_out, int out_size) {
    const float* x    = (const float*)d_in[0];
    const float* ea   = (const float*)d_in[1];
    const float* ew   = (const float*)d_in[2];
    const float* eb   = (const float*)d_in[3];
    const float* nw   = (const float*)d_in[4];
    const float* nb   = (const float*)d_in[5];
    const float* fcw  = (const float*)d_in[6];
    const float* fcb  = (const float*)d_in[7];
    const int*   ei   = (const int*)d_in[8];
    const int*   batch= (const int*)d_in[9];
    float* out = (float*)d_out;

    __half* xh; cudaGetSymbolAddress((void**)&xh, g_xh);
    __half* h0; cudaGetSymbolAddress((void**)&h0, g_h0);
    __half* h1; cudaGetSymbolAddress((void**)&h1, g_h1);

    k_pre  <<<EB2 + CVB, 256>>>(ei, ea, x);        // #1 edges pass1 + fp16 convert
    k_scan1<<<NB_NODES + 1, 256>>>(ew, eb, nw);    // #2
    k_edge2<<<EB2, 256>>>(ei);                     // #3

    const int LB = (N_NODES + 63) / 64;            // 782
    k_layer<<<LB, 256>>>(xh, h0, nw, nb, 0, 0, fcw, batch);   // #4 -> profiled
    k_layer<<<LB, 256>>>(h0, h1, nw, nb, 1, 0, fcw, batch);   // #5
    k_layer<<<LB, 256>>>(h1, h0, nw, nb, 2, 1, fcw, batch);   // #6 fused pooling

    k_out<<<NB_NODES + 1, 256>>>(out, fcb, batch); // #7 output + cleanup
}

// round 5
// speedup vs baseline: 1.5092x; 1.0033x over previous
#include <cuda_runtime.h>
#include <cuda_fp16.h>

#define N_NODES 50000
#define N_EDGES 800000
#define HID 64
#define N_LAYERS 3
#define N_GRAPHS 64
#define NB_NODES 196        // ceil(50000/256)
#define EB2 1563            // ceil(800000/2/256)
#define CVB 6250            // N_NODES*32 float2 / 256

// ---------------- scratch (device globals; zero-initialized at module load) ----------------
__device__ __half g_xh[N_NODES * HID];   // fp16 copy of input features
__device__ __half g_h0[N_NODES * HID];
__device__ __half g_h1[N_NODES * HID];
__device__ int    g_deg[N_NODES];        // zero at entry (k_out restores)
__device__ int    g_rowptr[N_NODES];
__device__ int    g_fill[N_NODES];
__device__ int    g_perm[N_EDGES];
__device__ float  g_sattr[N_NODES];      // zero at entry (k_out restores)
__device__ float  g_c1[N_LAYERS][HID];
__device__ float  g_c2[N_LAYERS][HID];
__device__ float  g_gsum[N_GRAPHS];      // zeroed in k_scan1

// ---------------- #1: edge pass 1 (deg + sattr) fused with fp32->fp16 convert ----------------
__global__ void k_pre(const int* __restrict__ ei, const float* __restrict__ ea,
                      const float* __restrict__ x) {
    if (blockIdx.x < EB2) {
        int p = blockIdx.x * 256 + threadIdx.x;
        int e = p * 2;
        if (e >= N_EDGES) return;
        int2   d2 = *(const int2*)  (ei + N_EDGES + e);
        float2 a2 = *(const float2*)(ea + e);
        atomicAdd(&g_deg[d2.x], 1);
        atomicAdd(&g_sattr[d2.x], a2.x);
        atomicAdd(&g_deg[d2.y], 1);
        atomicAdd(&g_sattr[d2.y], a2.y);
    } else {
        int i = (blockIdx.x - EB2) * 256 + threadIdx.x;   // float2 index
        if (i < N_NODES * 32) {
            float2 v = ((const float2*)x)[i];
            ((__half2*)g_xh)[i] = __floats2half2_rn(v.x, v.y);
        }
    }
}

// ---------------- #2: scan (redundant-prefix) + rank-2 constants + gsum zero ----------------
__global__ void __launch_bounds__(256) k_scan1(const float* __restrict__ ew,
                                               const float* __restrict__ eb,
                                               const float* __restrict__ nw) {
    const int b = blockIdx.x, tid = threadIdx.x;
    if (b == NB_NODES) {
        if (tid < N_GRAPHS) g_gsum[tid] = 0.f;
        if (tid >= N_LAYERS * HID) return;
        int l = tid / HID, h = tid % HID;
        float a = 0.f, c = 0.f;
        for (int k = 0; k < HID; k++) {
            float w = nw[(l * 2 * HID + HID + k) * HID + h];  // W2[k][h]
            a += ew[l * HID + k] * w;
            c += eb[l * HID + k] * w;
        }
        g_c1[l][h] = a;
        g_c2[l][h] = c;
        return;
    }

    __shared__ int sW[8];
    __shared__ int sBase;
    const int lane = tid & 31, w = tid >> 5;

    const int4* __restrict__ d4 = (const int4*)g_deg;
    const int nq = b * 64;
    int s = 0;
    for (int j = tid; j < nq; j += 256) {
        int4 v = d4[j];
        s += v.x + v.y + v.z + v.w;
    }
#pragma unroll
    for (int o = 16; o; o >>= 1) s += __shfl_down_sync(0xffffffffu, s, o);
    if (lane == 0) sW[w] = s;
    __syncthreads();
    if (tid == 0) {
        int t = 0;
#pragma unroll
        for (int j = 0; j < 8; j++) t += sW[j];
        sBase = t;
    }
    __syncthreads();
    const int base = sBase;
    __syncthreads();

    int i = b * 256 + tid;
    int v = (i < N_NODES) ? g_deg[i] : 0;
    int inc = v;
#pragma unroll
    for (int o = 1; o < 32; o <<= 1) {
        int t = __shfl_up_sync(0xffffffffu, inc, o);
        if (lane >= o) inc += t;
    }
    if (lane == 31) sW[w] = inc;
    __syncthreads();
    int wo = 0;
    for (int j = 0; j < w; j++) wo += sW[j];
    int exc = base + wo + inc - v;
    if (i < N_NODES) { g_rowptr[i] = exc; g_fill[i] = exc; }
}

// ---------------- #3: edge pass 2: CSR bucket placement ----------------
__global__ void k_edge2(const int* __restrict__ ei) {
    int p = blockIdx.x * blockDim.x + threadIdx.x;
    int e = p * 2;
    if (e >= N_EDGES) return;
    int2 s2 = *(const int2*)(ei + e);
    int2 d2 = *(const int2*)(ei + N_EDGES + e);
    int pos0 = atomicAdd(&g_fill[d2.x], 1);
    g_perm[pos0] = s2.x;
    int pos1 = atomicAdd(&g_fill[d2.y], 1);
    g_perm[pos1] = s2.y;
}

// ---------------- #4-6: fused layer: gather (fp16) + MLP (8 nodes/warp) + ReLU (+pool) ----------------
__global__ void __launch_bounds__(256) k_layer(
    const __half* __restrict__ xin, __half* __restrict__ xout,
    const float* __restrict__ nw, const float* __restrict__ nb, int l,
    int last, const float* __restrict__ fcw, const int* __restrict__ batch)
{
    __shared__ float2 sW2[HID][32];     // sW2[k][j] = (W1[k][2j], W1[k][2j+1])  16KB
    __shared__ float  sA[8][8][HID];    // [warp][node j][k]                      16KB
    const int tid = threadIdx.x;

    {
        const float2* __restrict__ nw2 = (const float2*)(nw + (size_t)l * 2 * HID * HID);
        for (int i = tid; i < HID * 32; i += 256) {
            int k = i >> 5, j = i & 31;
            sW2[k][j] = nw2[k * 32 + j];
        }
    }
    __syncthreads();

    const int warp = tid >> 5, lane = tid & 31;
    const int nbase = blockIdx.x * 64 + warp * 8;

    const float2 c1v = ((const float2*)g_c1[l])[lane];
    const float2 c2v = ((const float2*)g_c2[l])[lane];
    const float2 bv  = ((const float2*)(nb + l * HID))[lane];
    const __half2* __restrict__ xh2 = (const __half2*)xin;

    // ---- gather: 8 nodes per warp, whole warp covers one 128B row per edge ----
#pragma unroll
    for (int j = 0; j < 8; j++) {
        const int n = nbase + j;
        int beg = 0, cnt = 0;
        if (n < N_NODES) { beg = g_rowptr[n]; cnt = g_deg[n]; }
        float ax0 = 0.f, ay0 = 0.f, ax1 = 0.f, ay1 = 0.f;
        float ax2 = 0.f, ay2 = 0.f, ax3 = 0.f, ay3 = 0.f;
        for (int i = 0; i < cnt; i += 4) {
            const int* __restrict__ pp = g_perm + beg + i;
            const int rem = cnt - i;
            int s0 = pp[0];
            int s1 = (rem > 1) ? pp[1] : s0;
            int s2 = (rem > 2) ? pp[2] : s0;
            int s3 = (rem > 3) ? pp[3] : s0;
            float2 v0 = __half22float2(xh2[s0 * 32 + lane]);
            float2 v1 = __half22float2(xh2[s1 * 32 + lane]);
            float2 v2 = __half22float2(xh2[s2 * 32 + lane]);
            float2 v3 = __half22float2(xh2[s3 * 32 + lane]);
            ax0 += v0.x; ay0 += v0.y;
            if (rem > 1) { ax1 += v1.x; ay1 += v1.y; }
            if (rem > 2) { ax2 += v2.x; ay2 += v2.y; }
            if (rem > 3) { ax3 += v3.x; ay3 += v3.y; }
        }
        float ax = (ax0 + ax1) + (ax2 + ax3);
        float ay = (ay0 + ay1) + (ay2 + ay3);
        ((float2*)sA[warp][j])[lane] = make_float2(ax, ay);   // A[j][2lane], A[j][2lane+1]
    }
    __syncwarp();

    // ---- MLP: weights fetched once per warp per k-block, reused for 8 nodes ----
    float o0[8], o1[8];
#pragma unroll
    for (int j = 0; j < 8; j++) { o0[j] = 0.f; o1[j] = 0.f; }

#pragma unroll
    for (int kk = 0; kk < 16; kk++) {
        const float2 w0 = sW2[4 * kk + 0][lane];
        const float2 w1 = sW2[4 * kk + 1][lane];
        const float2 w2 = sW2[4 * kk + 2][lane];
        const float2 w3 = sW2[4 * kk + 3][lane];
#pragma unroll
        for (int j = 0; j < 8; j++) {
            const float4 a = ((const float4*)sA[warp][j])[kk];  // broadcast, 1 phase
            o0[j] += a.x * w0.x + a.y * w1.x + a.z * w2.x + a.w * w3.x;
            o1[j] += a.x * w0.y + a.y * w1.y + a.z * w2.y + a.w * w3.y;
        }
    }

    // ---- epilogue: rank-2 edge part + bias + ReLU, write fp16 (or pool on last) ----
    const float2 fw = last ? ((const float2*)fcw)[lane] : make_float2(0.f, 0.f);
#pragma unroll
    for (int j = 0; j < 8; j++) {
        const int n = nbase + j;
        if (n >= N_NODES) break;
        const float sa = g_sattr[n];
        const float dg = (float)g_deg[n];
        float u0 = o0[j] + sa * c1v.x + dg * c2v.x + bv.x;
        float u1 = o1[j] + sa * c1v.y + dg * c2v.y + bv.y;
        u0 = fmaxf(u0, 0.f);   // ReLU; LeakyReLU identity on >= 0
        u1 = fmaxf(u1, 0.f);
        if (!last) {
            ((__half2*)xout)[n * 32 + lane] = __floats2half2_rn(u0, u1);
        } else {
            float s = u0 * fw.x + u1 * fw.y;
#pragma unroll
            for (int off = 16; off; off >>= 1) s += __shfl_down_sync(0xffffffffu, s, off);
            if (lane == 0) atomicAdd(&g_gsum[batch[n]], s);
        }
    }
}

// ---------------- #7: final output (block 0) + scratch cleanup (blocks 1..) ----------------
__global__ void k_out(float* __restrict__ out, const float* __restrict__ fcb,
                      const int* __restrict__ batch) {
    if (blockIdx.x == 0) {
        int g = threadIdx.x;
        if (g >= N_GRAPHS) return;
        int lo = 0, hi = N_NODES;
        while (lo < hi) { int m = (lo + hi) >> 1; if (batch[m] < g) lo = m + 1; else hi = m; }
        int lo2 = lo, hi2 = N_NODES;
        while (lo2 < hi2) { int m = (lo2 + hi2) >> 1; if (batch[m] < g + 1) lo2 = m + 1; else hi2 = m; }
        float c = (float)(lo2 - lo);
        out[g] = g_gsum[g] / fmaxf(c, 1.f) + fcb[0];
    } else {
        int i = (blockIdx.x - 1) * 256 + threadIdx.x;
        if (i < N_NODES) { g_deg[i] = 0; g_sattr[i] = 0.f; }
    }
}

// ---------------- launch ----------------
extern "C" void kernel_launch(void* const* d_in, const int* in_sizes, int n_in,
                              void* d_out, int out_size) {
    const float* x    = (const float*)d_in[0];
    const float* ea   = (const float*)d_in[1];
    const float* ew   = (const float*)d_in[2];
    const float* eb   = (const float*)d_in[3];
    const float* nw   = (const float*)d_in[4];
    const float* nb   = (const float*)d_in[5];
    const float* fcw  = (const float*)d_in[6];
    const float* fcb  = (const float*)d_in[7];
    const int*   ei   = (const int*)d_in[8];
    const int*   batch= (const int*)d_in[9];
    float* out = (float*)d_out;

    __half* xh; cudaGetSymbolAddress((void**)&xh, g_xh);
    __half* h0; cudaGetSymbolAddress((void**)&h0, g_h0);
    __half* h1; cudaGetSymbolAddress((void**)&h1, g_h1);

    k_pre  <<<EB2 + CVB, 256>>>(ei, ea, x);        // #1 edges pass1 + fp16 convert
    k_scan1<<<NB_NODES + 1, 256>>>(ew, eb, nw);    // #2
    k_edge2<<<EB2, 256>>>(ei);                     // #3

    const int LB = (N_NODES + 63) / 64;            // 782
    k_layer<<<LB, 256>>>(xh, h0, nw, nb, 0, 0, fcw, batch);   // #4 -> profiled
    k_layer<<<LB, 256>>>(h0, h1, nw, nb, 1, 0, fcw, batch);   // #5
    k_layer<<<LB, 256>>>(h1, h0, nw, nb, 2, 1, fcw, batch);   // #6 fused pooling

    k_out<<<NB_NODES + 1, 256>>>(out, fcb, batch); // #7 output + cleanup
}

// round 6
// speedup vs baseline: 1.5448x; 1.0236x over previous
#include <cuda_runtime.h>
#include <cuda_fp16.h>

#define N_NODES 50000
#define N_EDGES 800000
#define HID 64
#define N_LAYERS 3
#define N_GRAPHS 64
#define NB_NODES 196        // ceil(50000/256)
#define EB2 1563            // ceil(800000/2/256)
#define CVB 6250            // N_NODES*32 float2 / 256
#define FULL 0xffffffffu

// ---------------- scratch (device globals; zero-initialized at module load) ----------------
__device__ __half g_xh[N_NODES * HID];
__device__ __half g_h0[N_NODES * HID];
__device__ __half g_h1[N_NODES * HID];
__device__ int    g_deg[N_NODES];        // zero at entry (k_out restores)
__device__ int    g_rowptr[N_NODES];
__device__ int    g_fill[N_NODES];
__device__ int    g_perm[N_EDGES];
__device__ float  g_sattr[N_NODES];      // zero at entry (k_out restores)
__device__ float  g_c1[N_LAYERS][HID];
__device__ float  g_c2[N_LAYERS][HID];
__device__ float  g_gsum[N_GRAPHS];      // zeroed in k_scan1
__device__ int    g_ctr[N_LAYERS];       // work-steal counters, zeroed in k_scan1

// ---------------- #1: edge pass 1 (deg + sattr) fused with fp32->fp16 convert ----------------
__global__ void k_pre(const int* __restrict__ ei, const float* __restrict__ ea,
                      const float* __restrict__ x) {
    if (blockIdx.x < EB2) {
        int p = blockIdx.x * 256 + threadIdx.x;
        int e = p * 2;
        if (e >= N_EDGES) return;
        int2   d2 = *(const int2*)  (ei + N_EDGES + e);
        float2 a2 = *(const float2*)(ea + e);
        atomicAdd(&g_deg[d2.x], 1);
        atomicAdd(&g_sattr[d2.x], a2.x);
        atomicAdd(&g_deg[d2.y], 1);
        atomicAdd(&g_sattr[d2.y], a2.y);
    } else {
        int i = (blockIdx.x - EB2) * 256 + threadIdx.x;   // float2 index
        if (i < N_NODES * 32) {
            float2 v = ((const float2*)x)[i];
            ((__half2*)g_xh)[i] = __floats2half2_rn(v.x, v.y);
        }
    }
}

// ---------------- #2: scan (redundant-prefix) + rank-2 constants + counters ----------------
__global__ void __launch_bounds__(256) k_scan1(const float* __restrict__ ew,
                                               const float* __restrict__ eb,
                                               const float* __restrict__ nw) {
    const int b = blockIdx.x, tid = threadIdx.x;
    if (b == NB_NODES) {
        if (tid < N_GRAPHS) g_gsum[tid] = 0.f;
        if (tid < N_LAYERS) g_ctr[tid] = 0;
        if (tid >= N_LAYERS * HID) return;
        int l = tid / HID, h = tid % HID;
        float a = 0.f, c = 0.f;
        for (int k = 0; k < HID; k++) {
            float w = nw[(l * 2 * HID + HID + k) * HID + h];  // W2[k][h]
            a += ew[l * HID + k] * w;
            c += eb[l * HID + k] * w;
        }
        g_c1[l][h] = a;
        g_c2[l][h] = c;
        return;
    }

    __shared__ int sW[8];
    __shared__ int sBase;
    const int lane = tid & 31, w = tid >> 5;

    const int4* __restrict__ d4 = (const int4*)g_deg;
    const int nq = b * 64;
    int s = 0;
    for (int j = tid; j < nq; j += 256) {
        int4 v = d4[j];
        s += v.x + v.y + v.z + v.w;
    }
#pragma unroll
    for (int o = 16; o; o >>= 1) s += __shfl_down_sync(FULL, s, o);
    if (lane == 0) sW[w] = s;
    __syncthreads();
    if (tid == 0) {
        int t = 0;
#pragma unroll
        for (int j = 0; j < 8; j++) t += sW[j];
        sBase = t;
    }
    __syncthreads();
    const int base = sBase;
    __syncthreads();

    int i = b * 256 + tid;
    int v = (i < N_NODES) ? g_deg[i] : 0;
    int inc = v;
#pragma unroll
    for (int o = 1; o < 32; o <<= 1) {
        int t = __shfl_up_sync(FULL, inc, o);
        if (lane >= o) inc += t;
    }
    if (lane == 31) sW[w] = inc;
    __syncthreads();
    int wo = 0;
    for (int j = 0; j < w; j++) wo += sW[j];
    int exc = base + wo + inc - v;
    if (i < N_NODES) { g_rowptr[i] = exc; g_fill[i] = exc; }
}

// ---------------- #3: edge pass 2: CSR bucket placement ----------------
__global__ void k_edge2(const int* __restrict__ ei) {
    int p = blockIdx.x * blockDim.x + threadIdx.x;
    int e = p * 2;
    if (e >= N_EDGES) return;
    int2 s2 = *(const int2*)(ei + e);
    int2 d2 = *(const int2*)(ei + N_EDGES + e);
    int pos0 = atomicAdd(&g_fill[d2.x], 1);
    g_perm[pos0] = s2.x;
    int pos1 = atomicAdd(&g_fill[d2.y], 1);
    g_perm[pos1] = s2.y;
}

// ---------------- #4-6: fused layer, work-stealing, 4 nodes/warp interleaved ----------------
__global__ void __launch_bounds__(256) k_layer(
    const __half* __restrict__ xin, __half* __restrict__ xout,
    const float* __restrict__ nw, const float* __restrict__ nb, int l,
    int last, const float* __restrict__ fcw, const int* __restrict__ batch)
{
    __shared__ float2 sW2[HID][32];     // (W1[k][2j], W1[k][2j+1])   16KB
    __shared__ float  sA[8][4][HID];    // [warp][node][k]             8KB
    const int tid = threadIdx.x;

    {
        const float2* __restrict__ nw2 = (const float2*)(nw + (size_t)l * 2 * HID * HID);
        for (int i = tid; i < HID * 32; i += 256) {
            int k = i >> 5, j = i & 31;
            sW2[k][j] = nw2[k * 32 + j];
        }
    }
    __syncthreads();

    const int warp = tid >> 5, lane = tid & 31;
    const float2 c1v = ((const float2*)g_c1[l])[lane];
    const float2 c2v = ((const float2*)g_c2[l])[lane];
    const float2 bv  = ((const float2*)(nb + l * HID))[lane];
    const float2 fw  = last ? ((const float2*)fcw)[lane] : make_float2(0.f, 0.f);
    const __half2* __restrict__ xh2 = (const __half2*)xin;

    for (;;) {
        int base;
        if (lane == 0) base = atomicAdd(&g_ctr[l], 4);
        base = __shfl_sync(FULL, base, 0);
        if (base >= N_NODES) break;

        // fetch rowptr/deg for 4 nodes via lanes 0..3
        int bp = 0, dp = 0;
        if (lane < 4 && base + lane < N_NODES) {
            bp = g_rowptr[base + lane];
            dp = g_deg[base + lane];
        }
        int beg[4], cnt[4];
#pragma unroll
        for (int j = 0; j < 4; j++) {
            beg[j] = __shfl_sync(FULL, bp, j);
            cnt[j] = __shfl_sync(FULL, dp, j);
        }
        int maxc = max(max(cnt[0], cnt[1]), max(cnt[2], cnt[3]));

        float ax[4] = {0.f, 0.f, 0.f, 0.f};
        float ay[4] = {0.f, 0.f, 0.f, 0.f};

#pragma unroll 2
        for (int i = 0; i < maxc; i += 2) {
            // lanes 0..7 fetch this round's perm indices (2 edges x 4 nodes)
            int pv = 0;
            {
                int j = lane >> 1, g = lane & 1;
                if (lane < 8 && i + g < cnt[j]) pv = g_perm[beg[j] + i + g];
            }
#pragma unroll
            for (int j = 0; j < 4; j++) {
                int s0 = __shfl_sync(FULL, pv, 2 * j);
                int s1 = __shfl_sync(FULL, pv, 2 * j + 1);
                if (i < cnt[j]) {            // warp-uniform
                    float2 v = __half22float2(xh2[s0 * 32 + lane]);
                    ax[j] += v.x; ay[j] += v.y;
                }
                if (i + 1 < cnt[j]) {
                    float2 v = __half22float2(xh2[s1 * 32 + lane]);
                    ax[j] += v.x; ay[j] += v.y;
                }
            }
        }

#pragma unroll
        for (int j = 0; j < 4; j++)
            ((float2*)sA[warp][j])[lane] = make_float2(ax[j], ay[j]);
        __syncwarp();

        // MLP: weights fetched once per k-block, reused across 4 nodes
        float o0[4] = {0.f, 0.f, 0.f, 0.f};
        float o1[4] = {0.f, 0.f, 0.f, 0.f};
#pragma unroll
        for (int kk = 0; kk < 16; kk++) {
            const float2 w0 = sW2[4 * kk + 0][lane];
            const float2 w1 = sW2[4 * kk + 1][lane];
            const float2 w2 = sW2[4 * kk + 2][lane];
            const float2 w3 = sW2[4 * kk + 3][lane];
#pragma unroll
            for (int j = 0; j < 4; j++) {
                const float4 a = ((const float4*)sA[warp][j])[kk];  // broadcast
                o0[j] += a.x * w0.x + a.y * w1.x + a.z * w2.x + a.w * w3.x;
                o1[j] += a.x * w0.y + a.y * w1.y + a.z * w2.y + a.w * w3.y;
            }
        }
        __syncwarp();

        // epilogue: rank-2 edge term + bias + ReLU; store fp16 or pool
#pragma unroll
        for (int j = 0; j < 4; j++) {
            const int n = base + j;
            if (n >= N_NODES) break;
            const float sa = g_sattr[n];
            const float dg = (float)cnt[j];
            float u0 = o0[j] + sa * c1v.x + dg * c2v.x + bv.x;
            float u1 = o1[j] + sa * c1v.y + dg * c2v.y + bv.y;
            u0 = fmaxf(u0, 0.f);   // ReLU; LeakyReLU identity on >= 0
            u1 = fmaxf(u1, 0.f);
            if (!last) {
                ((__half2*)xout)[n * 32 + lane] = __floats2half2_rn(u0, u1);
            } else {
                float s = u0 * fw.x + u1 * fw.y;
#pragma unroll
                for (int off = 16; off; off >>= 1) s += __shfl_down_sync(FULL, s, off);
                if (lane == 0) atomicAdd(&g_gsum[batch[n]], s);
            }
        }
    }
}

// ---------------- #7: final output (block 0) + scratch cleanup (blocks 1..) ----------------
__global__ void k_out(float* __restrict__ out, const float* __restrict__ fcb,
                      const int* __restrict__ batch) {
    if (blockIdx.x == 0) {
        int g = threadIdx.x;
        if (g >= N_GRAPHS) return;
        int lo = 0, hi = N_NODES;
        while (lo < hi) { int m = (lo + hi) >> 1; if (batch[m] < g) lo = m + 1; else hi = m; }
        int lo2 = lo, hi2 = N_NODES;
        while (lo2 < hi2) { int m = (lo2 + hi2) >> 1; if (batch[m] < g + 1) lo2 = m + 1; else hi2 = m; }
        float c = (float)(lo2 - lo);
        out[g] = g_gsum[g] / fmaxf(c, 1.f) + fcb[0];
    } else {
        int i = (blockIdx.x - 1) * 256 + threadIdx.x;
        if (i < N_NODES) { g_deg[i] = 0; g_sattr[i] = 0.f; }
    }
}

// ---------------- launch ----------------
extern "C" void kernel_launch(void* const* d_in, const int* in_sizes, int n_in,
                              void* d_out, int out_size) {
    const float* x    = (const float*)d_in[0];
    const float* ea   = (const float*)d_in[1];
    const float* ew   = (const float*)d_in[2];
    const float* eb   = (const float*)d_in[3];
    const float* nw   = (const float*)d_in[4];
    const float* nb   = (const float*)d_in[5];
    const float* fcw  = (const float*)d_in[6];
    const float* fcb  = (const float*)d_in[7];
    const int*   ei   = (const int*)d_in[8];
    const int*   batch= (const int*)d_in[9];
    float* out = (float*)d_out;

    __half* xh; cudaGetSymbolAddress((void**)&xh, g_xh);
    __half* h0; cudaGetSymbolAddress((void**)&h0, g_h0);
    __half* h1; cudaGetSymbolAddress((void**)&h1, g_h1);

    k_pre  <<<EB2 + CVB, 256>>>(ei, ea, x);        // #1
    k_scan1<<<NB_NODES + 1, 256>>>(ew, eb, nw);    // #2
    k_edge2<<<EB2, 256>>>(ei);                     // #3

    const int LB = 592;                            // 4 blocks/SM, work-stealing
    k_layer<<<LB, 256>>>(xh, h0, nw, nb, 0, 0, fcw, batch);   // #4 -> profiled
    k_layer<<<LB, 256>>>(h0, h1, nw, nb, 1, 0, fcw, batch);   // #5
    k_layer<<<LB, 256>>>(h1, h0, nw, nb, 2, 1, fcw, batch);   // #6 fused pooling

    k_out<<<NB_NODES + 1, 256>>>(out, fcb, batch); // #7 output + cleanup
}

// round 7
// speedup vs baseline: 1.7350x; 1.1231x over previous
#include <cuda_runtime.h>
#include <cuda_fp16.h>

#define N_NODES 50000
#define N_EDGES 800000
#define HID 64
#define N_LAYERS 3
#define N_GRAPHS 64
#define NB_NODES 196        // ceil(50000/256)
#define EB2 1563            // ceil(800000/2/256)
#define CVB 6250            // N_NODES*32 float2 / 256
#define FULL 0xffffffffu

// ---------------- scratch (device globals; zero-initialized at module load) ----------------
__device__ __half g_xh[N_NODES * HID];
__device__ __half g_h0[N_NODES * HID];
__device__ __half g_h1[N_NODES * HID];
__device__ int    g_deg[N_NODES];        // zero at entry (k_out restores)
__device__ int    g_rowptr[N_NODES];
__device__ int    g_fill[N_NODES];
__device__ int    g_perm[N_EDGES];
__device__ float  g_sattr[N_NODES];      // zero at entry (k_out restores)
__device__ float  g_c1[N_LAYERS][HID];
__device__ float  g_c2[N_LAYERS][HID];
__device__ float  g_gsum[N_GRAPHS];      // zeroed in k_scan1
__device__ int    g_ctr[N_LAYERS];       // work-steal counters, zeroed in k_scan1

// ---------------- #1: edge pass 1 (deg + sattr) fused with fp32->fp16 convert ----------------
__global__ void k_pre(const int* __restrict__ ei, const float* __restrict__ ea,
                      const float* __restrict__ x) {
    if (blockIdx.x < EB2) {
        int p = blockIdx.x * 256 + threadIdx.x;
        int e = p * 2;
        if (e >= N_EDGES) return;
        int2   d2 = *(const int2*)  (ei + N_EDGES + e);
        float2 a2 = *(const float2*)(ea + e);
        atomicAdd(&g_deg[d2.x], 1);
        atomicAdd(&g_sattr[d2.x], a2.x);
        atomicAdd(&g_deg[d2.y], 1);
        atomicAdd(&g_sattr[d2.y], a2.y);
    } else {
        int i = (blockIdx.x - EB2) * 256 + threadIdx.x;   // float2 index
        if (i < N_NODES * 32) {
            float2 v = ((const float2*)x)[i];
            ((__half2*)g_xh)[i] = __floats2half2_rn(v.x, v.y);
        }
    }
}

// ---------------- #2: scan (redundant-prefix) + rank-2 constants + counters ----------------
__global__ void __launch_bounds__(256) k_scan1(const float* __restrict__ ew,
                                               const float* __restrict__ eb,
                                               const float* __restrict__ nw) {
    const int b = blockIdx.x, tid = threadIdx.x;
    if (b == NB_NODES) {
        if (tid < N_GRAPHS) g_gsum[tid] = 0.f;
        if (tid < N_LAYERS) g_ctr[tid] = 0;
        if (tid >= N_LAYERS * HID) return;
        int l = tid / HID, h = tid % HID;
        float a = 0.f, c = 0.f;
        for (int k = 0; k < HID; k++) {
            float w = nw[(l * 2 * HID + HID + k) * HID + h];  // W2[k][h]
            a += ew[l * HID + k] * w;
            c += eb[l * HID + k] * w;
        }
        g_c1[l][h] = a;
        g_c2[l][h] = c;
        return;
    }

    __shared__ int sW[8];
    __shared__ int sBase;
    const int lane = tid & 31, w = tid >> 5;

    const int4* __restrict__ d4 = (const int4*)g_deg;
    const int nq = b * 64;
    int s = 0;
    for (int j = tid; j < nq; j += 256) {
        int4 v = d4[j];
        s += v.x + v.y + v.z + v.w;
    }
#pragma unroll
    for (int o = 16; o; o >>= 1) s += __shfl_down_sync(FULL, s, o);
    if (lane == 0) sW[w] = s;
    __syncthreads();
    if (tid == 0) {
        int t = 0;
#pragma unroll
        for (int j = 0; j < 8; j++) t += sW[j];
        sBase = t;
    }
    __syncthreads();
    const int base = sBase;
    __syncthreads();

    int i = b * 256 + tid;
    int v = (i < N_NODES) ? g_deg[i] : 0;
    int inc = v;
#pragma unroll
    for (int o = 1; o < 32; o <<= 1) {
        int t = __shfl_up_sync(FULL, inc, o);
        if (lane >= o) inc += t;
    }
    if (lane == 31) sW[w] = inc;
    __syncthreads();
    int wo = 0;
    for (int j = 0; j < w; j++) wo += sW[j];
    int exc = base + wo + inc - v;
    if (i < N_NODES) { g_rowptr[i] = exc; g_fill[i] = exc; }
}

// ---------------- #3: edge pass 2: CSR bucket placement ----------------
__global__ void k_edge2(const int* __restrict__ ei) {
    int p = blockIdx.x * blockDim.x + threadIdx.x;
    int e = p * 2;
    if (e >= N_EDGES) return;
    int2 s2 = *(const int2*)(ei + e);
    int2 d2 = *(const int2*)(ei + N_EDGES + e);
    int pos0 = atomicAdd(&g_fill[d2.x], 1);
    g_perm[pos0] = s2.x;
    int pos1 = atomicAdd(&g_fill[d2.y], 1);
    g_perm[pos1] = s2.y;
}

// ---------------- #4-6: fused layer: LDG.128 quarter-warp gather + amortized MLP ----------------
__global__ void __launch_bounds__(256) k_layer(
    const __half* __restrict__ xin, __half* __restrict__ xout,
    const float* __restrict__ nw, const float* __restrict__ nb, int l,
    int last, const float* __restrict__ fcw, const int* __restrict__ batch)
{
    __shared__ float2 sW2[HID][32];     // (W1[k][2j], W1[k][2j+1])   16KB
    __shared__ float  sA[8][4][HID];    // [warp][node][k]             8KB
    const int tid = threadIdx.x;

    {
        const float2* __restrict__ nw2 = (const float2*)(nw + (size_t)l * 2 * HID * HID);
        for (int i = tid; i < HID * 32; i += 256) {
            int k = i >> 5, j = i & 31;
            sW2[k][j] = nw2[k * 32 + j];
        }
    }
    __syncthreads();

    const int warp = tid >> 5, lane = tid & 31;
    const int q = lane >> 3, c = lane & 7;   // quarter-warp id, column-block
    const float2 c1v = ((const float2*)g_c1[l])[lane];
    const float2 c2v = ((const float2*)g_c2[l])[lane];
    const float2 bv  = ((const float2*)(nb + l * HID))[lane];
    const float2 fw  = last ? ((const float2*)fcw)[lane] : make_float2(0.f, 0.f);
    const uint4* __restrict__ xh4 = (const uint4*)xin;   // 8 halves per lane

    for (;;) {
        int base;
        if (lane == 0) base = atomicAdd(&g_ctr[l], 4);
        base = __shfl_sync(FULL, base, 0);
        if (base >= N_NODES) break;

        int bp = 0, dp = 0;
        if (lane < 4 && base + lane < N_NODES) {
            bp = g_rowptr[base + lane];
            dp = g_deg[base + lane];
        }
        int beg[4], cnt[4];
#pragma unroll
        for (int j = 0; j < 4; j++) {
            beg[j] = __shfl_sync(FULL, bp, j);
            cnt[j] = __shfl_sync(FULL, dp, j);
        }

        // ---- gather: each quarter-warp covers one edge row (128B) per round ----
#pragma unroll
        for (int j = 0; j < 4; j++) {
            float a0 = 0.f, a1 = 0.f, a2 = 0.f, a3 = 0.f;
            float a4 = 0.f, a5 = 0.f, a6 = 0.f, a7 = 0.f;
            const int cj = cnt[j], bj = beg[j];
#pragma unroll 2
            for (int i = 0; i < cj; i += 4) {
                const int e = i + q;
                const bool p = e < cj;
                const int idx = g_perm[bj + (p ? e : 0)];   // broadcast within quarter
                const uint4 v = xh4[idx * 8 + c];           // LDG.128: 4 rows / warp
                if (p) {
                    float2 f0 = __half22float2(*(const __half2*)&v.x);
                    float2 f1 = __half22float2(*(const __half2*)&v.y);
                    float2 f2 = __half22float2(*(const __half2*)&v.z);
                    float2 f3 = __half22float2(*(const __half2*)&v.w);
                    a0 += f0.x; a1 += f0.y; a2 += f1.x; a3 += f1.y;
                    a4 += f2.x; a5 += f2.y; a6 += f3.x; a7 += f3.y;
                }
            }
            // cross-quarter reduce (lanes l, l^8, l^16, l^24)
            a0 += __shfl_xor_sync(FULL, a0, 8);  a0 += __shfl_xor_sync(FULL, a0, 16);
            a1 += __shfl_xor_sync(FULL, a1, 8);  a1 += __shfl_xor_sync(FULL, a1, 16);
            a2 += __shfl_xor_sync(FULL, a2, 8);  a2 += __shfl_xor_sync(FULL, a2, 16);
            a3 += __shfl_xor_sync(FULL, a3, 8);  a3 += __shfl_xor_sync(FULL, a3, 16);
            a4 += __shfl_xor_sync(FULL, a4, 8);  a4 += __shfl_xor_sync(FULL, a4, 16);
            a5 += __shfl_xor_sync(FULL, a5, 8);  a5 += __shfl_xor_sync(FULL, a5, 16);
            a6 += __shfl_xor_sync(FULL, a6, 8);  a6 += __shfl_xor_sync(FULL, a6, 16);
            a7 += __shfl_xor_sync(FULL, a7, 8);  a7 += __shfl_xor_sync(FULL, a7, 16);
            if (q == 0) {
                ((float4*)sA[warp][j])[2 * c + 0] = make_float4(a0, a1, a2, a3);
                ((float4*)sA[warp][j])[2 * c + 1] = make_float4(a4, a5, a6, a7);
            }
        }
        __syncwarp();

        // ---- MLP: weights fetched once per k-block, reused across 4 nodes ----
        float o0[4] = {0.f, 0.f, 0.f, 0.f};
        float o1[4] = {0.f, 0.f, 0.f, 0.f};
#pragma unroll
        for (int kk = 0; kk < 16; kk++) {
            const float2 w0 = sW2[4 * kk + 0][lane];
            const float2 w1 = sW2[4 * kk + 1][lane];
            const float2 w2 = sW2[4 * kk + 2][lane];
            const float2 w3 = sW2[4 * kk + 3][lane];
#pragma unroll
            for (int j = 0; j < 4; j++) {
                const float4 a = ((const float4*)sA[warp][j])[kk];  // broadcast
                o0[j] += a.x * w0.x + a.y * w1.x + a.z * w2.x + a.w * w3.x;
                o1[j] += a.x * w0.y + a.y * w1.y + a.z * w2.y + a.w * w3.y;
            }
        }
        __syncwarp();

        // ---- epilogue: rank-2 edge term + bias + ReLU; store fp16 or pool ----
#pragma unroll
        for (int j = 0; j < 4; j++) {
            const int n = base + j;
            if (n >= N_NODES) break;
            const float sa = g_sattr[n];
            const float dg = (float)cnt[j];
            float u0 = o0[j] + sa * c1v.x + dg * c2v.x + bv.x;
            float u1 = o1[j] + sa * c1v.y + dg * c2v.y + bv.y;
            u0 = fmaxf(u0, 0.f);   // ReLU; LeakyReLU identity on >= 0
            u1 = fmaxf(u1, 0.f);
            if (!last) {
                ((__half2*)xout)[n * 32 + lane] = __floats2half2_rn(u0, u1);
            } else {
                float s = u0 * fw.x + u1 * fw.y;
#pragma unroll
                for (int off = 16; off; off >>= 1) s += __shfl_down_sync(FULL, s, off);
                if (lane == 0) atomicAdd(&g_gsum[batch[n]], s);
            }
        }
    }
}

// ---------------- #7: final output (block 0) + scratch cleanup (blocks 1..) ----------------
__global__ void k_out(float* __restrict__ out, const float* __restrict__ fcb,
                      const int* __restrict__ batch) {
    if (blockIdx.x == 0) {
        int g = threadIdx.x;
        if (g >= N_GRAPHS) return;
        int lo = 0, hi = N_NODES;
        while (lo < hi) { int m = (lo + hi) >> 1; if (batch[m] < g) lo = m + 1; else hi = m; }
        int lo2 = lo, hi2 = N_NODES;
        while (lo2 < hi2) { int m = (lo2 + hi2) >> 1; if (batch[m] < g + 1) lo2 = m + 1; else hi2 = m; }
        float c = (float)(lo2 - lo);
        out[g] = g_gsum[g] / fmaxf(c, 1.f) + fcb[0];
    } else {
        int i = (blockIdx.x - 1) * 256 + threadIdx.x;
        if (i < N_NODES) { g_deg[i] = 0; g_sattr[i] = 0.f; }
    }
}

// ---------------- launch ----------------
extern "C" void kernel_launch(void* const* d_in, const int* in_sizes, int n_in,
                              void* d_out, int out_size) {
    const float* x    = (const float*)d_in[0];
    const float* ea   = (const float*)d_in[1];
    const float* ew   = (const float*)d_in[2];
    const float* eb   = (const float*)d_in[3];
    const float* nw   = (const float*)d_in[4];
    const float* nb   = (const float*)d_in[5];
    const float* fcw  = (const float*)d_in[6];
    const float* fcb  = (const float*)d_in[7];
    const int*   ei   = (const int*)d_in[8];
    const int*   batch= (const int*)d_in[9];
    float* out = (float*)d_out;

    __half* xh; cudaGetSymbolAddress((void**)&xh, g_xh);
    __half* h0; cudaGetSymbolAddress((void**)&h0, g_h0);
    __half* h1; cudaGetSymbolAddress((void**)&h1, g_h1);

    k_pre  <<<EB2 + CVB, 256>>>(ei, ea, x);        // #1
    k_scan1<<<NB_NODES + 1, 256>>>(ew, eb, nw);    // #2
    k_edge2<<<EB2, 256>>>(ei);                     // #3

    const int LB = 592;                            // 4 blocks/SM, work-stealing
    k_layer<<<LB, 256>>>(xh, h0, nw, nb, 0, 0, fcw, batch);   // #4 -> profiled
    k_layer<<<LB, 256>>>(h0, h1, nw, nb, 1, 0, fcw, batch);   // #5
    k_layer<<<LB, 256>>>(h1, h0, nw, nb, 2, 1, fcw, batch);   // #6 fused pooling

    k_out<<<NB_NODES + 1, 256>>>(out, fcb, batch); // #7 output + cleanup
}

// round 8
// speedup vs baseline: 1.7703x; 1.0204x over previous
#include <cuda_runtime.h>
#include <cuda_fp16.h>

#define N_NODES 50000
#define N_EDGES 800000
#define HID 64
#define N_LAYERS 3
#define N_GRAPHS 64
#define NB_NODES 196        // ceil(50000/256)
#define EB2 1563            // ceil(800000/2/256)
#define CVB 6250            // N_NODES*32 float2 / 256
#define FULL 0xffffffffu
#define WSTRIDE 68          // sWt row stride in floats (16B-aligned, conflict-free)

#define FFMA2(acc, a, b) \
    asm("fma.rn.f32x2 %0, %1, %2, %3;" : "=l"(acc) : "l"(a), "l"(b), "l"(acc))

// ---------------- scratch (device globals; zero-initialized at module load) ----------------
__device__ __half g_xh[N_NODES * HID];
__device__ __half g_h0[N_NODES * HID];
__device__ __half g_h1[N_NODES * HID];
__device__ int    g_deg[N_NODES];        // zero at entry (k_out restores)
__device__ int    g_rowptr[N_NODES];
__device__ int    g_fill[N_NODES];
__device__ int    g_perm[N_EDGES];
__device__ float  g_sattr[N_NODES];      // zero at entry (k_out restores)
__device__ float  g_c1[N_LAYERS][HID];
__device__ float  g_c2[N_LAYERS][HID];
__device__ float  g_gsum[N_GRAPHS];      // zeroed in k_scan1
__device__ int    g_ctr[N_LAYERS];       // work-steal counters, zeroed in k_scan1

// ---------------- #1: edge pass 1 (deg + sattr) fused with fp32->fp16 convert ----------------
__global__ void k_pre(const int* __restrict__ ei, const float* __restrict__ ea,
                      const float* __restrict__ x) {
    if (blockIdx.x < EB2) {
        int p = blockIdx.x * 256 + threadIdx.x;
        int e = p * 2;
        if (e >= N_EDGES) return;
        int2   d2 = *(const int2*)  (ei + N_EDGES + e);
        float2 a2 = *(const float2*)(ea + e);
        atomicAdd(&g_deg[d2.x], 1);
        atomicAdd(&g_sattr[d2.x], a2.x);
        atomicAdd(&g_deg[d2.y], 1);
        atomicAdd(&g_sattr[d2.y], a2.y);
    } else {
        int i = (blockIdx.x - EB2) * 256 + threadIdx.x;   // float2 index
        if (i < N_NODES * 32) {
            float2 v = ((const float2*)x)[i];
            ((__half2*)g_xh)[i] = __floats2half2_rn(v.x, v.y);
        }
    }
}

// ---------------- #2: scan (redundant-prefix) + rank-2 constants + counters ----------------
__global__ void __launch_bounds__(256) k_scan1(const float* __restrict__ ew,
                                               const float* __restrict__ eb,
                                               const float* __restrict__ nw) {
    const int b = blockIdx.x, tid = threadIdx.x;
    if (b == NB_NODES) {
        if (tid < N_GRAPHS) g_gsum[tid] = 0.f;
        if (tid < N_LAYERS) g_ctr[tid] = 0;
        if (tid >= N_LAYERS * HID) return;
        int l = tid / HID, h = tid % HID;
        float a = 0.f, c = 0.f;
        for (int k = 0; k < HID; k++) {
            float w = nw[(l * 2 * HID + HID + k) * HID + h];  // W2[k][h]
            a += ew[l * HID + k] * w;
            c += eb[l * HID + k] * w;
        }
        g_c1[l][h] = a;
        g_c2[l][h] = c;
        return;
    }

    __shared__ int sW[8];
    __shared__ int sBase;
    const int lane = tid & 31, w = tid >> 5;

    const int4* __restrict__ d4 = (const int4*)g_deg;
    const int nq = b * 64;
    int s = 0;
    for (int j = tid; j < nq; j += 256) {
        int4 v = d4[j];
        s += v.x + v.y + v.z + v.w;
    }
#pragma unroll
    for (int o = 16; o; o >>= 1) s += __shfl_down_sync(FULL, s, o);
    if (lane == 0) sW[w] = s;
    __syncthreads();
    if (tid == 0) {
        int t = 0;
#pragma unroll
        for (int j = 0; j < 8; j++) t += sW[j];
        sBase = t;
    }
    __syncthreads();
    const int base = sBase;
    __syncthreads();

    int i = b * 256 + tid;
    int v = (i < N_NODES) ? g_deg[i] : 0;
    int inc = v;
#pragma unroll
    for (int o = 1; o < 32; o <<= 1) {
        int t = __shfl_up_sync(FULL, inc, o);
        if (lane >= o) inc += t;
    }
    if (lane == 31) sW[w] = inc;
    __syncthreads();
    int wo = 0;
    for (int j = 0; j < w; j++) wo += sW[j];
    int exc = base + wo + inc - v;
    if (i < N_NODES) { g_rowptr[i] = exc; g_fill[i] = exc; }
}

// ---------------- #3: edge pass 2: CSR bucket placement ----------------
__global__ void k_edge2(const int* __restrict__ ei) {
    int p = blockIdx.x * blockDim.x + threadIdx.x;
    int e = p * 2;
    if (e >= N_EDGES) return;
    int2 s2 = *(const int2*)(ei + e);
    int2 d2 = *(const int2*)(ei + N_EDGES + e);
    int pos0 = atomicAdd(&g_fill[d2.x], 1);
    g_perm[pos0] = s2.x;
    int pos1 = atomicAdd(&g_fill[d2.y], 1);
    g_perm[pos1] = s2.y;
}

// ---------------- #4-6: fused layer: LDG.128 gather + f32x2-packed MLP ----------------
__global__ void __launch_bounds__(256, 5) k_layer(
    const __half* __restrict__ xin, __half* __restrict__ xout,
    const float* __restrict__ nw, const float* __restrict__ nb, int l,
    int last, const float* __restrict__ fcw, const int* __restrict__ batch)
{
    __shared__ float sWt[HID * WSTRIDE];   // transposed W1: sWt[h*68 + k] = W1[k][h], 17KB
    __shared__ float sA[8][4][HID];        // [warp][node][k]                            8KB
    const int tid = threadIdx.x;

    // stage W1 transposed: consecutive tid -> consecutive h (coalesced gmem reads)
    {
        const float* __restrict__ nwl = nw + (size_t)l * 2 * HID * HID;
        for (int i = tid; i < HID * HID; i += 256) {
            int h = i & 63, k = i >> 6;
            sWt[h * WSTRIDE + k] = nwl[k * HID + h];
        }
    }
    __syncthreads();

    const int warp = tid >> 5, lane = tid & 31;
    const int q = lane >> 3, c = lane & 7;   // quarter-warp id, column-block
    // output columns: h0 = lane, h1 = lane + 32
    const float c1a = g_c1[l][lane], c1b = g_c1[l][lane + 32];
    const float c2a = g_c2[l][lane], c2b = g_c2[l][lane + 32];
    const float ba  = nb[l * HID + lane], bb = nb[l * HID + lane + 32];
    const float fwa = last ? fcw[lane] : 0.f;
    const float fwb = last ? fcw[lane + 32] : 0.f;
    const uint4* __restrict__ xh4 = (const uint4*)xin;   // 8 halves per lane

    for (;;) {
        int base;
        if (lane == 0) base = atomicAdd(&g_ctr[l], 4);
        base = __shfl_sync(FULL, base, 0);
        if (base >= N_NODES) break;

        int bp = 0, dp = 0;
        if (lane < 4 && base + lane < N_NODES) {
            bp = g_rowptr[base + lane];
            dp = g_deg[base + lane];
        }
        int beg[4], cnt[4];
#pragma unroll
        for (int j = 0; j < 4; j++) {
            beg[j] = __shfl_sync(FULL, bp, j);
            cnt[j] = __shfl_sync(FULL, dp, j);
        }

        // ---- gather: each quarter-warp covers one edge row (128B) per round ----
#pragma unroll
        for (int j = 0; j < 4; j++) {
            float a0 = 0.f, a1 = 0.f, a2 = 0.f, a3 = 0.f;
            float a4 = 0.f, a5 = 0.f, a6 = 0.f, a7 = 0.f;
            const int cj = cnt[j], bj = beg[j];
#pragma unroll 2
            for (int i = 0; i < cj; i += 4) {
                const int e = i + q;
                const bool p = e < cj;
                const int idx = g_perm[bj + (p ? e : 0)];   // broadcast within quarter
                const uint4 v = xh4[idx * 8 + c];           // LDG.128: 4 rows / warp
                if (p) {
                    float2 f0 = __half22float2(*(const __half2*)&v.x);
                    float2 f1 = __half22float2(*(const __half2*)&v.y);
                    float2 f2 = __half22float2(*(const __half2*)&v.z);
                    float2 f3 = __half22float2(*(const __half2*)&v.w);
                    a0 += f0.x; a1 += f0.y; a2 += f1.x; a3 += f1.y;
                    a4 += f2.x; a5 += f2.y; a6 += f3.x; a7 += f3.y;
                }
            }
            // cross-quarter reduce (lanes l, l^8, l^16, l^24)
            a0 += __shfl_xor_sync(FULL, a0, 8);  a0 += __shfl_xor_sync(FULL, a0, 16);
            a1 += __shfl_xor_sync(FULL, a1, 8);  a1 += __shfl_xor_sync(FULL, a1, 16);
            a2 += __shfl_xor_sync(FULL, a2, 8);  a2 += __shfl_xor_sync(FULL, a2, 16);
            a3 += __shfl_xor_sync(FULL, a3, 8);  a3 += __shfl_xor_sync(FULL, a3, 16);
            a4 += __shfl_xor_sync(FULL, a4, 8);  a4 += __shfl_xor_sync(FULL, a4, 16);
            a5 += __shfl_xor_sync(FULL, a5, 8);  a5 += __shfl_xor_sync(FULL, a5, 16);
            a6 += __shfl_xor_sync(FULL, a6, 8);  a6 += __shfl_xor_sync(FULL, a6, 16);
            a7 += __shfl_xor_sync(FULL, a7, 8);  a7 += __shfl_xor_sync(FULL, a7, 16);
            if (q == 0) {
                ((float4*)sA[warp][j])[2 * c + 0] = make_float4(a0, a1, a2, a3);
                ((float4*)sA[warp][j])[2 * c + 1] = make_float4(a4, a5, a6, a7);
            }
        }
        __syncwarp();

        // ---- MLP: packed f32x2 FMA along k; weights reused across 4 nodes ----
        unsigned long long o0p[4] = {0ull, 0ull, 0ull, 0ull};
        unsigned long long o1p[4] = {0ull, 0ull, 0ull, 0ull};
#pragma unroll
        for (int kk = 0; kk < 16; kk++) {
            const ulonglong2 w0 = *(const ulonglong2*)&sWt[lane * WSTRIDE + 4 * kk];
            const ulonglong2 w1 = *(const ulonglong2*)&sWt[(lane + 32) * WSTRIDE + 4 * kk];
#pragma unroll
            for (int j = 0; j < 4; j++) {
                const ulonglong2 av = *(const ulonglong2*)&sA[warp][j][4 * kk]; // broadcast
                FFMA2(o0p[j], av.x, w0.x);
                FFMA2(o0p[j], av.y, w0.y);
                FFMA2(o1p[j], av.x, w1.x);
                FFMA2(o1p[j], av.y, w1.y);
            }
        }
        __syncwarp();

        // ---- epilogue: horizontal add + rank-2 edge term + bias + ReLU ----
#pragma unroll
        for (int j = 0; j < 4; j++) {
            const int n = base + j;
            if (n >= N_NODES) break;
            float o0lo, o0hi, o1lo, o1hi;
            asm("mov.b64 {%0,%1}, %2;" : "=f"(o0lo), "=f"(o0hi) : "l"(o0p[j]));
            asm("mov.b64 {%0,%1}, %2;" : "=f"(o1lo), "=f"(o1hi) : "l"(o1p[j]));
            const float sa = g_sattr[n];
            const float dg = (float)cnt[j];
            float u0 = (o0lo + o0hi) + sa * c1a + dg * c2a + ba;
            float u1 = (o1lo + o1hi) + sa * c1b + dg * c2b + bb;
            u0 = fmaxf(u0, 0.f);   // ReLU; LeakyReLU identity on >= 0
            u1 = fmaxf(u1, 0.f);
            if (!last) {
                xout[n * HID + lane]      = __float2half_rn(u0);   // coalesced 64B
                xout[n * HID + lane + 32] = __float2half_rn(u1);   // coalesced 64B
            } else {
                float s = u0 * fwa + u1 * fwb;
#pragma unroll
                for (int off = 16; off; off >>= 1) s += __shfl_down_sync(FULL, s, off);
                if (lane == 0) atomicAdd(&g_gsum[batch[n]], s);
            }
        }
    }
}

// ---------------- #7: final output (block 0) + scratch cleanup (blocks 1..) ----------------
__global__ void k_out(float* __restrict__ out, const float* __restrict__ fcb,
                      const int* __restrict__ batch) {
    if (blockIdx.x == 0) {
        int g = threadIdx.x;
        if (g >= N_GRAPHS) return;
        int lo = 0, hi = N_NODES;
        while (lo < hi) { int m = (lo + hi) >> 1; if (batch[m] < g) lo = m + 1; else hi = m; }
        int lo2 = lo, hi2 = N_NODES;
        while (lo2 < hi2) { int m = (lo2 + hi2) >> 1; if (batch[m] < g + 1) lo2 = m + 1; else hi2 = m; }
        float c = (float)(lo2 - lo);
        out[g] = g_gsum[g] / fmaxf(c, 1.f) + fcb[0];
    } else {
        int i = (blockIdx.x - 1) * 256 + threadIdx.x;
        if (i < N_NODES) { g_deg[i] = 0; g_sattr[i] = 0.f; }
    }
}

// ---------------- launch ----------------
extern "C" void kernel_launch(void* const* d_in, const int* in_sizes, int n_in,
                              void* d_out, int out_size) {
    const float* x    = (const float*)d_in[0];
    const float* ea   = (const float*)d_in[1];
    const float* ew   = (const float*)d_in[2];
    const float* eb   = (const float*)d_in[3];
    const float* nw   = (const float*)d_in[4];
    const float* nb   = (const float*)d_in[5];
    const float* fcw  = (const float*)d_in[6];
    const float* fcb  = (const float*)d_in[7];
    const int*   ei   = (const int*)d_in[8];
    const int*   batch= (const int*)d_in[9];
    float* out = (float*)d_out;

    __half* xh; cudaGetSymbolAddress((void**)&xh, g_xh);
    __half* h0; cudaGetSymbolAddress((void**)&h0, g_h0);
    __half* h1; cudaGetSymbolAddress((void**)&h1, g_h1);

    k_pre  <<<EB2 + CVB, 256>>>(ei, ea, x);        // #1
    k_scan1<<<NB_NODES + 1, 256>>>(ew, eb, nw);    // #2
    k_edge2<<<EB2, 256>>>(ei);                     // #3

    const int LB = 740;                            // 5 blocks/SM, work-stealing
    k_layer<<<LB, 256>>>(xh, h0, nw, nb, 0, 0, fcw, batch);   // #4 -> profiled
    k_layer<<<LB, 256>>>(h0, h1, nw, nb, 1, 0, fcw, batch);   // #5
    k_layer<<<LB, 256>>>(h1, h0, nw, nb, 2, 1, fcw, batch);   // #6 fused pooling

    k_out<<<NB_NODES + 1, 256>>>(out, fcb, batch); // #7 output + cleanup
}

// round 9
// speedup vs baseline: 1.8649x; 1.0534x over previous
#include <cuda_runtime.h>
#include <cuda_fp16.h>

#define N_NODES 50000
#define N_EDGES 800000
#define HID 64
#define N_LAYERS 3
#define N_GRAPHS 64
#define NB_NODES 196        // ceil(50000/256)
#define EB2 1563            // ceil(800000/2/256)
#define CVB 6250            // N_NODES*32 float2 / 256
#define FULL 0xffffffffu
#define WSTRIDE 68          // sWt row stride in floats (16B-aligned, conflict-free)

#define FFMA2(acc, a, b) \
    asm("fma.rn.f32x2 %0, %1, %2, %3;" : "=l"(acc) : "l"(a), "l"(b), "l"(acc))

// ---------------- scratch (device globals; zero-initialized at module load) ----------------
__device__ __half g_xh[N_NODES * HID];
__device__ __half g_h0[N_NODES * HID];
__device__ __half g_h1[N_NODES * HID];
__device__ int    g_deg[N_NODES];        // zero at entry (k_out restores)
__device__ int    g_rowptr[N_NODES];
__device__ int    g_fill[N_NODES];
__device__ int    g_perm[N_EDGES];
__device__ float  g_sattr[N_NODES];      // zero at entry (k_out restores)
__device__ float  g_c1[N_LAYERS][HID];
__device__ float  g_c2[N_LAYERS][HID];
__device__ float  g_gsum[N_GRAPHS];      // zeroed in k_scan1
__device__ int    g_ctr[N_LAYERS];       // work-steal counters, zeroed in k_scan1

// ---------------- #1: edge pass 1 (deg + sattr) fused with fp32->fp16 convert ----------------
__global__ void k_pre(const int* __restrict__ ei, const float* __restrict__ ea,
                      const float* __restrict__ x) {
    if (blockIdx.x < EB2) {
        int p = blockIdx.x * 256 + threadIdx.x;
        int e = p * 2;
        if (e >= N_EDGES) return;
        int2   d2 = *(const int2*)  (ei + N_EDGES + e);
        float2 a2 = *(const float2*)(ea + e);
        atomicAdd(&g_deg[d2.x], 1);
        atomicAdd(&g_sattr[d2.x], a2.x);
        atomicAdd(&g_deg[d2.y], 1);
        atomicAdd(&g_sattr[d2.y], a2.y);
    } else {
        int i = (blockIdx.x - EB2) * 256 + threadIdx.x;   // float2 index
        if (i < N_NODES * 32) {
            float2 v = ((const float2*)x)[i];
            ((__half2*)g_xh)[i] = __floats2half2_rn(v.x, v.y);
        }
    }
}

// ---------------- #2: scan (redundant-prefix) + rank-2 constants + counters ----------------
__global__ void __launch_bounds__(256) k_scan1(const float* __restrict__ ew,
                                               const float* __restrict__ eb,
                                               const float* __restrict__ nw) {
    const int b = blockIdx.x, tid = threadIdx.x;
    if (b == NB_NODES) {
        if (tid < N_GRAPHS) g_gsum[tid] = 0.f;
        if (tid < N_LAYERS) g_ctr[tid] = 0;
        if (tid >= N_LAYERS * HID) return;
        int l = tid / HID, h = tid % HID;
        float a = 0.f, c = 0.f;
        for (int k = 0; k < HID; k++) {
            float w = nw[(l * 2 * HID + HID + k) * HID + h];  // W2[k][h]
            a += ew[l * HID + k] * w;
            c += eb[l * HID + k] * w;
        }
        g_c1[l][h] = a;
        g_c2[l][h] = c;
        return;
    }

    __shared__ int sW[8];
    __shared__ int sBase;
    const int lane = tid & 31, w = tid >> 5;

    const int4* __restrict__ d4 = (const int4*)g_deg;
    const int nq = b * 64;
    int s = 0;
    for (int j = tid; j < nq; j += 256) {
        int4 v = d4[j];
        s += v.x + v.y + v.z + v.w;
    }
#pragma unroll
    for (int o = 16; o; o >>= 1) s += __shfl_down_sync(FULL, s, o);
    if (lane == 0) sW[w] = s;
    __syncthreads();
    if (tid == 0) {
        int t = 0;
#pragma unroll
        for (int j = 0; j < 8; j++) t += sW[j];
        sBase = t;
    }
    __syncthreads();
    const int base = sBase;
    __syncthreads();

    int i = b * 256 + tid;
    int v = (i < N_NODES) ? g_deg[i] : 0;
    int inc = v;
#pragma unroll
    for (int o = 1; o < 32; o <<= 1) {
        int t = __shfl_up_sync(FULL, inc, o);
        if (lane >= o) inc += t;
    }
    if (lane == 31) sW[w] = inc;
    __syncthreads();
    int wo = 0;
    for (int j = 0; j < w; j++) wo += sW[j];
    int exc = base + wo + inc - v;
    if (i < N_NODES) { g_rowptr[i] = exc; g_fill[i] = exc; }
}

// ---------------- #3: edge pass 2: CSR bucket placement ----------------
__global__ void k_edge2(const int* __restrict__ ei) {
    int p = blockIdx.x * blockDim.x + threadIdx.x;
    int e = p * 2;
    if (e >= N_EDGES) return;
    int2 s2 = *(const int2*)(ei + e);
    int2 d2 = *(const int2*)(ei + N_EDGES + e);
    int pos0 = atomicAdd(&g_fill[d2.x], 1);
    g_perm[pos0] = s2.x;
    int pos1 = atomicAdd(&g_fill[d2.y], 1);
    g_perm[pos1] = s2.y;
}

// ---------------- #4-6: fused layer: quarter-owns-node gather + f32x2 MLP ----------------
__global__ void __launch_bounds__(256, 5) k_layer(
    const __half* __restrict__ xin, __half* __restrict__ xout,
    const float* __restrict__ nw, const float* __restrict__ nb, int l,
    int last, const float* __restrict__ fcw, const int* __restrict__ batch)
{
    __shared__ float sWt[HID * WSTRIDE];   // transposed W1: sWt[h*68+k] = W1[k][h], 17KB
    __shared__ float sA[8][4][HID];        // [warp][node][k]                          8KB
    const int tid = threadIdx.x;

    {
        const float* __restrict__ nwl = nw + (size_t)l * 2 * HID * HID;
        for (int i = tid; i < HID * HID; i += 256) {
            int h = i & 63, k = i >> 6;
            sWt[h * WSTRIDE + k] = nwl[k * HID + h];
        }
    }
    __syncthreads();

    const int warp = tid >> 5, lane = tid & 31;
    const int q = lane >> 3, c = lane & 7;   // quarter-warp id (= owned node), col-block
    const float c1a = g_c1[l][lane], c1b = g_c1[l][lane + 32];
    const float c2a = g_c2[l][lane], c2b = g_c2[l][lane + 32];
    const float ba  = nb[l * HID + lane], bb = nb[l * HID + lane + 32];
    const float fwa = last ? fcw[lane] : 0.f;
    const float fwb = last ? fcw[lane + 32] : 0.f;
    const uint4* __restrict__ xh4 = (const uint4*)xin;   // 8 halves per lane

    for (;;) {
        int base;
        if (lane == 0) base = atomicAdd(&g_ctr[l], 4);
        base = __shfl_sync(FULL, base, 0);
        if (base >= N_NODES) break;

        int bp = 0, dp = 0;
        if (lane < 4 && base + lane < N_NODES) {
            bp = g_rowptr[base + lane];
            dp = g_deg[base + lane];
        }
        // each quarter-warp owns node base+q
        const int bj = __shfl_sync(FULL, bp, q);
        const int cj = __shfl_sync(FULL, dp, q);

        // ---- gather: quarter walks its own edge list, 4 rows in flight ----
        float a0 = 0.f, a1 = 0.f, a2 = 0.f, a3 = 0.f;
        float a4 = 0.f, a5 = 0.f, a6 = 0.f, a7 = 0.f;
        {
            const int* __restrict__ pB = g_perm + bj;
            for (int i = 0; i < cj; i += 4) {
                const int rem = cj - i;
                const int s0 = pB[i];
                const int s1 = (rem > 1) ? pB[i + 1] : s0;
                const int s2 = (rem > 2) ? pB[i + 2] : s0;
                const int s3 = (rem > 3) ? pB[i + 3] : s0;
                const uint4 v0 = xh4[s0 * 8 + c];
                const uint4 v1 = xh4[s1 * 8 + c];
                const uint4 v2 = xh4[s2 * 8 + c];
                const uint4 v3 = xh4[s3 * 8 + c];
                {
                    float2 f0 = __half22float2(*(const __half2*)&v0.x);
                    float2 f1 = __half22float2(*(const __half2*)&v0.y);
                    float2 f2 = __half22float2(*(const __half2*)&v0.z);
                    float2 f3 = __half22float2(*(const __half2*)&v0.w);
                    a0 += f0.x; a1 += f0.y; a2 += f1.x; a3 += f1.y;
                    a4 += f2.x; a5 += f2.y; a6 += f3.x; a7 += f3.y;
                }
                if (rem > 1) {
                    float2 f0 = __half22float2(*(const __half2*)&v1.x);
                    float2 f1 = __half22float2(*(const __half2*)&v1.y);
                    float2 f2 = __half22float2(*(const __half2*)&v1.z);
                    float2 f3 = __half22float2(*(const __half2*)&v1.w);
                    a0 += f0.x; a1 += f0.y; a2 += f1.x; a3 += f1.y;
                    a4 += f2.x; a5 += f2.y; a6 += f3.x; a7 += f3.y;
                }
                if (rem > 2) {
                    float2 f0 = __half22float2(*(const __half2*)&v2.x);
                    float2 f1 = __half22float2(*(const __half2*)&v2.y);
                    float2 f2 = __half22float2(*(const __half2*)&v2.z);
                    float2 f3 = __half22float2(*(const __half2*)&v2.w);
                    a0 += f0.x; a1 += f0.y; a2 += f1.x; a3 += f1.y;
                    a4 += f2.x; a5 += f2.y; a6 += f3.x; a7 += f3.y;
                }
                if (rem > 3) {
                    float2 f0 = __half22float2(*(const __half2*)&v3.x);
                    float2 f1 = __half22float2(*(const __half2*)&v3.y);
                    float2 f2 = __half22float2(*(const __half2*)&v3.z);
                    float2 f3 = __half22float2(*(const __half2*)&v3.w);
                    a0 += f0.x; a1 += f0.y; a2 += f1.x; a3 += f1.y;
                    a4 += f2.x; a5 += f2.y; a6 += f3.x; a7 += f3.y;
                }
            }
        }
        // quarter owns all 64 cols of its node: direct stores, no reduction
        ((float4*)sA[warp][q])[2 * c + 0] = make_float4(a0, a1, a2, a3);
        ((float4*)sA[warp][q])[2 * c + 1] = make_float4(a4, a5, a6, a7);
        __syncwarp();

        // ---- MLP: packed f32x2 FMA along k; weights reused across 4 nodes ----
        unsigned long long o0p[4] = {0ull, 0ull, 0ull, 0ull};
        unsigned long long o1p[4] = {0ull, 0ull, 0ull, 0ull};
#pragma unroll
        for (int kk = 0; kk < 16; kk++) {
            const ulonglong2 w0 = *(const ulonglong2*)&sWt[lane * WSTRIDE + 4 * kk];
            const ulonglong2 w1 = *(const ulonglong2*)&sWt[(lane + 32) * WSTRIDE + 4 * kk];
#pragma unroll
            for (int j = 0; j < 4; j++) {
                const ulonglong2 av = *(const ulonglong2*)&sA[warp][j][4 * kk]; // broadcast
                FFMA2(o0p[j], av.x, w0.x);
                FFMA2(o0p[j], av.y, w0.y);
                FFMA2(o1p[j], av.x, w1.x);
                FFMA2(o1p[j], av.y, w1.y);
            }
        }
        __syncwarp();

        // ---- epilogue: horizontal add + rank-2 edge term + bias + ReLU ----
#pragma unroll
        for (int j = 0; j < 4; j++) {
            const int n = base + j;
            if (n >= N_NODES) break;
            float o0lo, o0hi, o1lo, o1hi;
            asm("mov.b64 {%0,%1}, %2;" : "=f"(o0lo), "=f"(o0hi) : "l"(o0p[j]));
            asm("mov.b64 {%0,%1}, %2;" : "=f"(o1lo), "=f"(o1hi) : "l"(o1p[j]));
            const float sa = g_sattr[n];
            const float dg = (float)__shfl_sync(FULL, dp, j);
            float u0 = (o0lo + o0hi) + sa * c1a + dg * c2a + ba;
            float u1 = (o1lo + o1hi) + sa * c1b + dg * c2b + bb;
            u0 = fmaxf(u0, 0.f);   // ReLU; LeakyReLU identity on >= 0
            u1 = fmaxf(u1, 0.f);
            if (!last) {
                xout[n * HID + lane]      = __float2half_rn(u0);
                xout[n * HID + lane + 32] = __float2half_rn(u1);
            } else {
                float s = u0 * fwa + u1 * fwb;
#pragma unroll
                for (int off = 16; off; off >>= 1) s += __shfl_down_sync(FULL, s, off);
                if (lane == 0) atomicAdd(&g_gsum[batch[n]], s);
            }
        }
    }
}

// ---------------- #7: final output (block 0) + scratch cleanup (blocks 1..) ----------------
__global__ void k_out(float* __restrict__ out, const float* __restrict__ fcb,
                      const int* __restrict__ batch) {
    if (blockIdx.x == 0) {
        int g = threadIdx.x;
        if (g >= N_GRAPHS) return;
        int lo = 0, hi = N_NODES;
        while (lo < hi) { int m = (lo + hi) >> 1; if (batch[m] < g) lo = m + 1; else hi = m; }
        int lo2 = lo, hi2 = N_NODES;
        while (lo2 < hi2) { int m = (lo2 + hi2) >> 1; if (batch[m] < g + 1) lo2 = m + 1; else hi2 = m; }
        float c = (float)(lo2 - lo);
        out[g] = g_gsum[g] / fmaxf(c, 1.f) + fcb[0];
    } else {
        int i = (blockIdx.x - 1) * 256 + threadIdx.x;
        if (i < N_NODES) { g_deg[i] = 0; g_sattr[i] = 0.f; }
    }
}

// ---------------- launch ----------------
extern "C" void kernel_launch(void* const* d_in, const int* in_sizes, int n_in,
                              void* d_out, int out_size) {
    const float* x    = (const float*)d_in[0];
    const float* ea   = (const float*)d_in[1];
    const float* ew   = (const float*)d_in[2];
    const float* eb   = (const float*)d_in[3];
    const float* nw   = (const float*)d_in[4];
    const float* nb   = (const float*)d_in[5];
    const float* fcw  = (const float*)d_in[6];
    const float* fcb  = (const float*)d_in[7];
    const int*   ei   = (const int*)d_in[8];
    const int*   batch= (const int*)d_in[9];
    float* out = (float*)d_out;

    __half* xh; cudaGetSymbolAddress((void**)&xh, g_xh);
    __half* h0; cudaGetSymbolAddress((void**)&h0, g_h0);
    __half* h1; cudaGetSymbolAddress((void**)&h1, g_h1);

    k_pre  <<<EB2 + CVB, 256>>>(ei, ea, x);        // #1
    k_scan1<<<NB_NODES + 1, 256>>>(ew, eb, nw);    // #2
    k_edge2<<<EB2, 256>>>(ei);                     // #3

    const int LB = 740;                            // 5 blocks/SM, work-stealing
    k_layer<<<LB, 256>>>(xh, h0, nw, nb, 0, 0, fcw, batch);   // #4 -> profiled
    k_layer<<<LB, 256>>>(h0, h1, nw, nb, 1, 0, fcw, batch);   // #5
    k_layer<<<LB, 256>>>(h1, h0, nw, nb, 2, 1, fcw, batch);   // #6 fused pooling

    k_out<<<NB_NODES + 1, 256>>>(out, fcb, batch); // #7 output + cleanup
}